// round 1
// baseline (speedup 1.0000x reference)
#include <cuda_runtime.h>
#include <math.h>

#define BB    256
#define TS    120
#define PREDN 24
#define NJ    15
#define HH    1024
#define DD    135
#define NF    61        // rfft length = TS/2+1
#define GG    3072      // 3*H
#define NHEAD 4
#define DHD   256       // H / NHEAD

// ---------------- scratch buffers (static device globals; no allocation) ----
// g_big holds gi (B,TS,3H). Earlier in the stream it also holds qkv (offset 0)
// and the attention output (offset B*NF*GG) -- both dead before gi is written.
__device__ float g_big[(size_t)BB * TS * GG];         // 94.4M floats
// g_seq holds seq0 (B,TS,H). Earlier it holds feat (B,NF,H) (dead before seq0 writes).
__device__ float g_seq[(size_t)BB * TS * HH];         // 31.5M floats
__device__ float g_in [(size_t)BB * TS * DD];         // contiguous input_seq
__device__ float g_frq[(size_t)BB * NF * DD];
__device__ float g_cosm[NF * TS];
__device__ float g_obar[BB * HH];
__device__ float g_mctx[BB * HH];
__device__ float g_h0[BB * HH];
__device__ float g_h1[BB * HH];
__device__ float g_gh[BB * GG];
__device__ float g_gx[BB * GG];
__device__ float g_hid[BB * HH];
__device__ float g_z1[BB * NJ * 128];
__device__ float g_xt[BB * DD];
__device__ float g_p6[BB * NJ * 6];

// ---------------- small utility kernels -------------------------------------

__global__ void copy_inseq_kernel(const float* __restrict__ poses, float* __restrict__ dst) {
    int idx = blockIdx.x * 256 + threadIdx.x;
    if (idx >= BB * TS * DD) return;
    int d = idx % DD;
    int t = (idx / DD) % TS;
    int b = idx / (TS * DD);
    dst[idx] = poses[((size_t)b * (TS + PREDN) + t) * DD + d];
}

__global__ void build_cos_kernel(float* __restrict__ cosm) {
    int idx = blockIdx.x * 256 + threadIdx.x;
    if (idx >= NF * TS) return;
    int f = idx / TS, t = idx % TS;
    cosm[idx] = (float)cos(2.0 * 3.14159265358979323846 * (double)(f * t) / (double)TS);
}

// freq[b,f,d] = sum_t cos[f,t] * inseq[b,t,d]
__global__ void freq_kernel(const float* __restrict__ inseq, const float* __restrict__ cosm,
                            float* __restrict__ freq) {
    int b = blockIdx.x, f = blockIdx.y, d = threadIdx.x;
    if (d >= DD) return;
    const float* xp = inseq + (size_t)b * TS * DD + d;
    const float* cp = cosm + f * TS;
    float s = 0.f;
    #pragma unroll 4
    for (int t = 0; t < TS; t++) s += cp[t] * xp[(size_t)t * DD];
    freq[((size_t)b * NF + f) * DD + d] = s;
}

// ---------------- generic fp32 GEMM: C = A(MxK) * W(NxK)^T + bias -----------
// act: 0 none, 1 relu.  addend (optional, MxN) added AFTER activation.
__global__ __launch_bounds__(256) void gemm_bias(
    const float* __restrict__ A, const float* __restrict__ W,
    const float* __restrict__ bias, const float* __restrict__ addend,
    float* __restrict__ C, int M, int N, int K, int act)
{
    __shared__ __align__(16) float As[16][68];
    __shared__ __align__(16) float Ws[16][68];
    int tid = threadIdx.x;
    int tx = tid & 15, ty = tid >> 4;
    int m0 = blockIdx.y * 64, n0 = blockIdx.x * 64;
    float acc[4][4] = {};

    for (int k0 = 0; k0 < K; k0 += 16) {
        #pragma unroll
        for (int i = 0; i < 4; i++) {
            int idx = tid + i * 256;      // 0..1023
            int r = idx >> 4, kk = idx & 15;
            int gk = k0 + kk;
            int gm = m0 + r;
            float va = 0.f;
            if (gm < M && gk < K) va = A[(size_t)gm * K + gk];
            As[kk][r] = va;
            int gn = n0 + r;
            float vw = 0.f;
            if (gn < N && gk < K) vw = W[(size_t)gn * K + gk];
            Ws[kk][r] = vw;
        }
        __syncthreads();
        #pragma unroll
        for (int kk = 0; kk < 16; kk++) {
            float4 a4 = *(const float4*)&As[kk][ty * 4];
            float4 b4 = *(const float4*)&Ws[kk][tx * 4];
            float av[4] = {a4.x, a4.y, a4.z, a4.w};
            float bv[4] = {b4.x, b4.y, b4.z, b4.w};
            #pragma unroll
            for (int i = 0; i < 4; i++)
                #pragma unroll
                for (int j = 0; j < 4; j++)
                    acc[i][j] += av[i] * bv[j];
        }
        __syncthreads();
    }
    #pragma unroll
    for (int i = 0; i < 4; i++) {
        int gm = m0 + ty * 4 + i;
        if (gm >= M) continue;
        #pragma unroll
        for (int j = 0; j < 4; j++) {
            int gn = n0 + tx * 4 + j;
            if (gn >= N) continue;
            float v = acc[i][j] + bias[gn];
            if (act == 1) v = fmaxf(v, 0.f);
            if (addend) v += addend[(size_t)gm * N + gn];
            C[(size_t)gm * N + gn] = v;
        }
    }
}

// ---------------- attention (per batch,head block) ---------------------------
__global__ __launch_bounds__(256) void attention_kernel(const float* __restrict__ qkv,
                                                        float* __restrict__ o) {
    extern __shared__ float sm[];         // kv: NF*DHD floats, sc: NF*64 floats
    float* kv = sm;
    float* sc = sm + NF * DHD;
    int b = blockIdx.x >> 2;
    int h = blockIdx.x & 3;
    int tid = threadIdx.x;
    int lane = tid & 31, w = tid >> 5;
    const float* base = qkv + (size_t)b * NF * GG + h * DHD;

    // load K into smem
    for (int idx = tid; idx < NF * DHD; idx += 256) {
        int t = idx >> 8, d = idx & 255;
        kv[idx] = base[(size_t)t * GG + HH + d];
    }
    __syncthreads();
    // scores
    for (int i = w; i < NF; i += 8) {
        float q[8];
        const float* qp = base + (size_t)i * GG;
        #pragma unroll
        for (int c = 0; c < 8; c++) q[c] = qp[lane + 32 * c];
        for (int j = 0; j < NF; j++) {
            const float* kp = kv + j * DHD;
            float s = 0.f;
            #pragma unroll
            for (int c = 0; c < 8; c++) s += q[c] * kp[lane + 32 * c];
            #pragma unroll
            for (int off = 16; off; off >>= 1) s += __shfl_xor_sync(0xffffffffu, s, off);
            if (lane == 0) sc[i * 64 + j] = s * 0.0625f;   // 1/sqrt(256)
        }
    }
    __syncthreads();
    // softmax rows
    for (int i = w; i < NF; i += 8) {
        float v0 = (lane < NF) ? sc[i * 64 + lane] : -1e30f;
        float v1 = (lane + 32 < NF) ? sc[i * 64 + lane + 32] : -1e30f;
        float m = fmaxf(v0, v1);
        #pragma unroll
        for (int off = 16; off; off >>= 1) m = fmaxf(m, __shfl_xor_sync(0xffffffffu, m, off));
        float e0 = (lane < NF) ? expf(v0 - m) : 0.f;
        float e1 = (lane + 32 < NF) ? expf(v1 - m) : 0.f;
        float ss = e0 + e1;
        #pragma unroll
        for (int off = 16; off; off >>= 1) ss += __shfl_xor_sync(0xffffffffu, ss, off);
        float inv = 1.f / ss;
        if (lane < NF) sc[i * 64 + lane] = e0 * inv;
        if (lane + 32 < NF) sc[i * 64 + lane + 32] = e1 * inv;
    }
    __syncthreads();
    // load V into smem (overwrites K)
    for (int idx = tid; idx < NF * DHD; idx += 256) {
        int t = idx >> 8, d = idx & 255;
        kv[idx] = base[(size_t)t * GG + 2 * HH + d];
    }
    __syncthreads();
    // output: thread owns column d = tid
    float acc[NF];
    #pragma unroll
    for (int i = 0; i < NF; i++) acc[i] = 0.f;
    int d = tid;
    for (int j = 0; j < NF; j++) {
        float vv = kv[j * DHD + d];
        #pragma unroll
        for (int i = 0; i < NF; i++) acc[i] += sc[i * 64 + j] * vv;
    }
    float* ob = o + (size_t)b * NF * HH + h * DHD + d;
    #pragma unroll
    for (int i = 0; i < NF; i++) ob[(size_t)i * HH] = acc[i];
}

__global__ void mean61_kernel(const float* __restrict__ o, float* __restrict__ obar) {
    int idx = blockIdx.x * 256 + threadIdx.x;
    if (idx >= BB * HH) return;
    int b = idx >> 10, c = idx & 1023;
    const float* p = o + (size_t)b * NF * HH + c;
    float s = 0.f;
    for (int t = 0; t < NF; t++) s += p[(size_t)t * HH];
    obar[idx] = s * (1.f / (float)NF);
}

// ---------------- GRU gate math ----------------------------------------------
__global__ void gru_gate(const float* __restrict__ gi, size_t gi_rs,
                         const float* __restrict__ gh,
                         float* __restrict__ h,
                         float* __restrict__ seqout, size_t seq_rs) {
    int idx = blockIdx.x * 256 + threadIdx.x;
    if (idx >= BB * HH) return;
    int b = idx >> 10, j = idx & 1023;
    const float* gib = gi + (size_t)b * gi_rs;
    const float* ghb = gh + (size_t)b * GG;
    float ir = gib[j],        hr = ghb[j];
    float iz = gib[HH + j],   hz = ghb[HH + j];
    float in = gib[2*HH + j], hn = ghb[2*HH + j];
    float r = 1.f / (1.f + expf(-(ir + hr)));
    float z = 1.f / (1.f + expf(-(iz + hz)));
    float n = tanhf(in + r * hn);
    float hp = h[idx];
    float hnew = (1.f - z) * n + z * hp;
    h[idx] = hnew;
    if (seqout) seqout[(size_t)b * seq_rs + j] = hnew;
}

// ---------------- decode init: x0 and prev6d ---------------------------------
__global__ void init_decode(const float* __restrict__ inseq,
                            float* __restrict__ xt, float* __restrict__ p6) {
    int idx = blockIdx.x * 256 + threadIdx.x;
    if (idx >= BB * DD) return;
    int b = idx / DD, d = idx % DD;
    const float* last = inseq + ((size_t)b * TS + (TS - 1)) * DD;
    xt[idx] = last[d];
    if (d < NJ * 6) {
        int j = d / 6, o = d % 6;
        int src = (o < 3) ? (j * 9 + o * 3) : (j * 9 + (o - 3) * 3 + 1);
        p6[(size_t)b * 90 + d] = last[src];
    }
}

// ---------------- spl head layer2 + 6d accumulate + rot6d->rotmat ------------
__global__ __launch_bounds__(192) void spl2_rot(const float* __restrict__ z1,
                                                const float* __restrict__ w2,
                                                const float* __restrict__ b2,
                                                float* __restrict__ p6,
                                                float* __restrict__ xt,
                                                float* __restrict__ out, int step) {
    int bj = blockIdx.x;
    int b = bj / NJ, j = bj % NJ;
    int w = threadIdx.x >> 5, lane = threadIdx.x & 31;
    __shared__ float v6[6];
    const float* zz = z1 + (size_t)b * (NJ * 128) + j * 128;
    const float* ww = w2 + ((size_t)j * 6 + w) * 128;
    float s = 0.f;
    #pragma unroll
    for (int c = 0; c < 4; c++) s += zz[lane + 32 * c] * ww[lane + 32 * c];
    #pragma unroll
    for (int off = 16; off; off >>= 1) s += __shfl_xor_sync(0xffffffffu, s, off);
    if (lane == 0)
        v6[w] = p6[(size_t)b * 90 + j * 6 + w] + s + b2[j * 6 + w];
    __syncthreads();
    if (threadIdx.x < 6) {
        float v = v6[threadIdx.x];
        p6[(size_t)b * 90 + j * 6 + threadIdx.x] = v;
        out[((size_t)b * PREDN + step) * 90 + j * 6 + threadIdx.x] = v;
    }
    if (threadIdx.x == 0) {
        // rot6d: reshape (3,2) -> a1=(v0,v2,v4), a2=(v1,v3,v5)
        float a1x = v6[0], a2x = v6[1], a1y = v6[2], a2y = v6[3], a1z = v6[4], a2z = v6[5];
        float n1 = fmaxf(sqrtf(a1x*a1x + a1y*a1y + a1z*a1z), 1e-12f);
        float b1x = a1x / n1, b1y = a1y / n1, b1z = a1z / n1;
        float dot = b1x*a2x + b1y*a2y + b1z*a2z;
        float ox = a2x - dot*b1x, oy = a2y - dot*b1y, oz = a2z - dot*b1z;
        float n2 = fmaxf(sqrtf(ox*ox + oy*oy + oz*oz), 1e-12f);
        float b2x = ox / n2, b2y = oy / n2, b2z = oz / n2;
        float b3x = b1y*b2z - b1z*b2y;
        float b3y = b1z*b2x - b1x*b2z;
        float b3z = b1x*b2y - b1y*b2x;
        float* xo = xt + (size_t)b * DD + j * 9;
        xo[0] = b1x; xo[1] = b2x; xo[2] = b3x;
        xo[3] = b1y; xo[4] = b2y; xo[5] = b3y;
        xo[6] = b1z; xo[7] = b2z; xo[8] = b3z;
    }
}

// ---------------- host orchestration -----------------------------------------

static inline void gemm(const float* A, const float* W, const float* bias,
                        const float* add, float* C, int M, int N, int K, int act) {
    dim3 g((N + 63) / 64, (M + 63) / 64);
    gemm_bias<<<g, 256>>>(A, W, bias, add, C, M, N, K, act);
}

extern "C" void kernel_launch(void* const* d_in, const int* in_sizes, int n_in,
                              void* d_out, int out_size) {
    const float* poses      = (const float*)d_in[0];
    const float* freq_w     = (const float*)d_in[1];
    const float* freq_b     = (const float*)d_in[2];
    const float* attn_in_w  = (const float*)d_in[3];
    const float* attn_in_b  = (const float*)d_in[4];
    const float* attn_out_w = (const float*)d_in[5];
    const float* attn_out_b = (const float*)d_in[6];
    const float* gru_wih0   = (const float*)d_in[7];
    const float* gru_whh0   = (const float*)d_in[8];
    const float* gru_bih0   = (const float*)d_in[9];
    const float* gru_bhh0   = (const float*)d_in[10];
    const float* gru_wih1   = (const float*)d_in[11];
    const float* gru_whh1   = (const float*)d_in[12];
    const float* gru_bih1   = (const float*)d_in[13];
    const float* gru_bhh1   = (const float*)d_in[14];
    const float* pre_w      = (const float*)d_in[15];
    const float* pre_b      = (const float*)d_in[16];
    const float* spl_w1     = (const float*)d_in[17];   // (15,128,1024) == (1920,1024)
    const float* spl_b1     = (const float*)d_in[18];   // (1920)
    const float* spl_w2     = (const float*)d_in[19];
    const float* spl_b2     = (const float*)d_in[20];
    float* out = (float*)d_out;

    float *pBig, *pSeq, *pIn, *pFrq, *pCos, *pObar, *pMctx, *pH0, *pH1, *pGh, *pGx,
          *pHid, *pZ1, *pXt, *pP6;
    cudaGetSymbolAddress((void**)&pBig, g_big);
    cudaGetSymbolAddress((void**)&pSeq, g_seq);
    cudaGetSymbolAddress((void**)&pIn,  g_in);
    cudaGetSymbolAddress((void**)&pFrq, g_frq);
    cudaGetSymbolAddress((void**)&pCos, g_cosm);
    cudaGetSymbolAddress((void**)&pObar, g_obar);
    cudaGetSymbolAddress((void**)&pMctx, g_mctx);
    cudaGetSymbolAddress((void**)&pH0, g_h0);
    cudaGetSymbolAddress((void**)&pH1, g_h1);
    cudaGetSymbolAddress((void**)&pGh, g_gh);
    cudaGetSymbolAddress((void**)&pGx, g_gx);
    cudaGetSymbolAddress((void**)&pHid, g_hid);
    cudaGetSymbolAddress((void**)&pZ1, g_z1);
    cudaGetSymbolAddress((void**)&pXt, g_xt);
    cudaGetSymbolAddress((void**)&pP6, g_p6);

    float* qkv   = pBig;                              // (B*NF, 3072)
    float* attno = pBig + (size_t)BB * NF * GG;       // (B*NF, 1024)
    float* gi    = pBig;                              // (B*TS, 3072)
    float* feat  = pSeq;                              // (B*NF, 1024)
    float* seq0  = pSeq;                              // (B*TS, 1024)

    const int BF = BB * NF;   // 15616
    const int BT = BB * TS;   // 30720

    // ---- frequency attention branch ----
    copy_inseq_kernel<<<(BB*TS*DD + 255) / 256, 256>>>(poses, pIn);
    build_cos_kernel<<<(NF*TS + 255) / 256, 256>>>(pCos);
    freq_kernel<<<dim3(BB, NF), 160>>>(pIn, pCos, pFrq);
    gemm(pFrq, freq_w, freq_b, nullptr, feat, BF, HH, DD, 0);
    gemm(feat, attn_in_w, attn_in_b, nullptr, qkv, BF, GG, HH, 0);

    int smem_attn = (NF * DHD + NF * 64) * (int)sizeof(float);   // 78080 B
    cudaFuncSetAttribute(attention_kernel, cudaFuncAttributeMaxDynamicSharedMemorySize, smem_attn);
    attention_kernel<<<BB * NHEAD, 256, smem_attn>>>(qkv, attno);
    mean61_kernel<<<(BB*HH + 255) / 256, 256>>>(attno, pObar);
    gemm(pObar, attn_out_w, attn_out_b, nullptr, pMctx, BB, HH, HH, 0);

    // ---- GRU layer 0 ----
    gemm(pIn, gru_wih0, gru_bih0, nullptr, gi, BT, GG, DD, 0);
    cudaMemsetAsync(pH0, 0, (size_t)BB * HH * sizeof(float));
    for (int t = 0; t < TS; t++) {
        gemm(pH0, gru_whh0, gru_bhh0, nullptr, pGh, BB, GG, HH, 0);
        gru_gate<<<(BB*HH)/256, 256>>>(gi + (size_t)t * GG, (size_t)TS * GG,
                                       pGh, pH0, seq0 + (size_t)t * HH, (size_t)TS * HH);
    }

    // ---- GRU layer 1 ----
    gemm(seq0, gru_wih1, gru_bih1, nullptr, gi, BT, GG, HH, 0);
    cudaMemsetAsync(pH1, 0, (size_t)BB * HH * sizeof(float));
    for (int t = 0; t < TS; t++) {
        gemm(pH1, gru_whh1, gru_bhh1, nullptr, pGh, BB, GG, HH, 0);
        gru_gate<<<(BB*HH)/256, 256>>>(gi + (size_t)t * GG, (size_t)TS * GG,
                                       pGh, pH1, nullptr, 0);
    }

    // ---- autoregressive decode ----
    init_decode<<<(BB*DD + 255) / 256, 256>>>(pIn, pXt, pP6);
    for (int s = 0; s < PREDN; s++) {
        gemm(pXt, gru_wih0, gru_bih0, nullptr, pGx, BB, GG, DD, 0);
        gemm(pH0, gru_whh0, gru_bhh0, nullptr, pGh, BB, GG, HH, 0);
        gru_gate<<<(BB*HH)/256, 256>>>(pGx, (size_t)GG, pGh, pH0, nullptr, 0);

        gemm(pH0, gru_wih1, gru_bih1, nullptr, pGx, BB, GG, HH, 0);
        gemm(pH1, gru_whh1, gru_bhh1, nullptr, pGh, BB, GG, HH, 0);
        gru_gate<<<(BB*HH)/256, 256>>>(pGx, (size_t)GG, pGh, pH1, nullptr, 0);

        gemm(pH1, pre_w, pre_b, pMctx, pHid, BB, HH, HH, 1);          // relu + motion_ctx
        gemm(pHid, spl_w1, spl_b1, nullptr, pZ1, BB, NJ * 128, HH, 1); // relu
        spl2_rot<<<BB * NJ, 192>>>(pZ1, spl_w2, spl_b2, pP6, pXt, out, s);
    }
}

// round 3
// speedup vs baseline: 1.0875x; 1.0875x over previous
#include <cuda_runtime.h>
#include <cuda_bf16.h>
#include <mma.h>
#include <math.h>

using namespace nvcuda;

#define BB    256
#define TS    120
#define PREDN 24
#define NJ    15
#define HH    1024
#define DD    135
#define NF    61        // rfft length = TS/2+1
#define GG    3072      // 3*H
#define NHEAD 4
#define DHD   256       // H / NHEAD

// ---------------- scratch buffers (static device globals; no allocation) ----
__device__ float g_big[(size_t)BB * TS * GG];         // gi / qkv / attn-out (aliased)
__device__ float g_seq[(size_t)BB * TS * HH];         // seq0 / feat (aliased)
__device__ float g_in [(size_t)BB * TS * DD];
__device__ float g_frq[(size_t)BB * NF * DD];
__device__ float g_cosm[NF * TS];
__device__ float g_obar[BB * HH];
__device__ float g_mctx[BB * HH];
__device__ float g_h0[BB * HH];
__device__ float g_h1[BB * HH];
__device__ float g_gh[BB * GG];
__device__ float g_gx[BB * GG];
__device__ float g_hid[BB * HH];
__device__ float g_z1[BB * NJ * 128];
__device__ float g_xt[BB * DD];
__device__ float g_p6[BB * NJ * 6];

// ---------------- small utility kernels -------------------------------------

__global__ void copy_inseq_kernel(const float* __restrict__ poses, float* __restrict__ dst) {
    int idx = blockIdx.x * 256 + threadIdx.x;
    if (idx >= BB * TS * DD) return;
    int d = idx % DD;
    int t = (idx / DD) % TS;
    int b = idx / (TS * DD);
    dst[idx] = poses[((size_t)b * (TS + PREDN) + t) * DD + d];
}

__global__ void build_cos_kernel(float* __restrict__ cosm) {
    int idx = blockIdx.x * 256 + threadIdx.x;
    if (idx >= NF * TS) return;
    int f = idx / TS, t = idx % TS;
    cosm[idx] = (float)cos(2.0 * 3.14159265358979323846 * (double)(f * t) / (double)TS);
}

// freq[b,f,d] = sum_t cos[f,t] * inseq[b,t,d]
__global__ void freq_kernel(const float* __restrict__ inseq, const float* __restrict__ cosm,
                            float* __restrict__ freq) {
    int b = blockIdx.x, f = blockIdx.y, d = threadIdx.x;
    if (d >= DD) return;
    const float* xp = inseq + (size_t)b * TS * DD + d;
    const float* cp = cosm + f * TS;
    float s = 0.f;
    #pragma unroll 4
    for (int t = 0; t < TS; t++) s += cp[t] * xp[(size_t)t * DD];
    freq[((size_t)b * NF + f) * DD + d] = s;
}

// ---------------- error-compensated bf16 GEMM --------------------------------
// C = act(A(MxK) * W(NxK)^T + bias), fp32 in/out.
// Each fp32 value is split x = hi + lo (hi = bf16(x), lo = bf16(x - hi)).
// acc += Ahi*Whi + Ahi*Wlo + Alo*Whi  (fp32 accumulate; lo*lo term ~2^-18, dropped)
// Requires M % 128 == 0 and N % 128 == 0 (true for all call sites).
// Bias fused via appended ones-column in A / bias-column in W (K -> K+1).
__global__ __launch_bounds__(256, 2) void gemm_bf16c(
    const float* __restrict__ A, const float* __restrict__ W,
    const float* __restrict__ bias, float* __restrict__ C,
    int M, int N, int K, int act)
{
    __shared__ __align__(16) __nv_bfloat16 AsH[128][40];
    __shared__ __align__(16) __nv_bfloat16 AsL[128][40];
    __shared__ __align__(16) __nv_bfloat16 WsH[128][40];
    __shared__ __align__(16) __nv_bfloat16 WsL[128][40];

    int tid = threadIdx.x;
    int warp = tid >> 5;
    int wm = warp >> 1, wn = warp & 1;     // 4x2 warp grid, warp tile 32x64
    int m0 = blockIdx.y * 128, n0 = blockIdx.x * 128;

    wmma::fragment<wmma::accumulator, 16, 16, 16, float> acc[2][4];
    #pragma unroll
    for (int i = 0; i < 2; i++)
        #pragma unroll
        for (int j = 0; j < 4; j++)
            wmma::fill_fragment(acc[i][j], 0.0f);

    int col  = tid & 31;     // k within chunk
    int row0 = tid >> 5;     // 0..7
    int KE = K + 1;          // bias column

    for (int k0 = 0; k0 < KE; k0 += 32) {
        if (k0 + 32 <= K) {
            #pragma unroll
            for (int i = 0; i < 16; i++) {
                int r = row0 + i * 8;
                float va = A[(size_t)(m0 + r) * K + k0 + col];
                float vw = W[(size_t)(n0 + r) * K + k0 + col];
                __nv_bfloat16 ah = __float2bfloat16(va);
                __nv_bfloat16 wh = __float2bfloat16(vw);
                AsH[r][col] = ah;
                AsL[r][col] = __float2bfloat16(va - __bfloat162float(ah));
                WsH[r][col] = wh;
                WsL[r][col] = __float2bfloat16(vw - __bfloat162float(wh));
            }
        } else {
            int gk = k0 + col;
            #pragma unroll
            for (int i = 0; i < 16; i++) {
                int r = row0 + i * 8;
                float va = 0.f, vw = 0.f;
                if (gk < K) {
                    va = A[(size_t)(m0 + r) * K + gk];
                    vw = W[(size_t)(n0 + r) * K + gk];
                } else if (gk == K) {
                    va = 1.0f;
                    vw = bias[n0 + r];
                }
                __nv_bfloat16 ah = __float2bfloat16(va);
                __nv_bfloat16 wh = __float2bfloat16(vw);
                AsH[r][col] = ah;
                AsL[r][col] = __float2bfloat16(va - __bfloat162float(ah));
                WsH[r][col] = wh;
                WsL[r][col] = __float2bfloat16(vw - __bfloat162float(wh));
            }
        }
        __syncthreads();
        #pragma unroll
        for (int kk = 0; kk < 32; kk += 16) {
            wmma::fragment<wmma::matrix_a, 16, 16, 16, __nv_bfloat16, wmma::row_major> faH[2], faL[2];
            #pragma unroll
            for (int i = 0; i < 2; i++) {
                wmma::load_matrix_sync(faH[i], &AsH[wm * 32 + i * 16][kk], 40);
                wmma::load_matrix_sync(faL[i], &AsL[wm * 32 + i * 16][kk], 40);
            }
            #pragma unroll
            for (int j = 0; j < 4; j++) {
                wmma::fragment<wmma::matrix_b, 16, 16, 16, __nv_bfloat16, wmma::col_major> fbH, fbL;
                wmma::load_matrix_sync(fbH, &WsH[wn * 64 + j * 16][kk], 40);
                wmma::load_matrix_sync(fbL, &WsL[wn * 64 + j * 16][kk], 40);
                #pragma unroll
                for (int i = 0; i < 2; i++) {
                    wmma::mma_sync(acc[i][j], faH[i], fbH, acc[i][j]);
                    wmma::mma_sync(acc[i][j], faH[i], fbL, acc[i][j]);
                    wmma::mma_sync(acc[i][j], faL[i], fbH, acc[i][j]);
                }
            }
        }
        __syncthreads();
    }

    #pragma unroll
    for (int i = 0; i < 2; i++) {
        #pragma unroll
        for (int j = 0; j < 4; j++) {
            if (act == 1) {
                #pragma unroll
                for (int e = 0; e < acc[i][j].num_elements; e++)
                    acc[i][j].x[e] = fmaxf(acc[i][j].x[e], 0.0f);
            }
            wmma::store_matrix_sync(
                C + (size_t)(m0 + wm * 32 + i * 16) * N + (n0 + wn * 64 + j * 16),
                acc[i][j], N, wmma::mem_row_major);
        }
    }
}

// ---------------- attention (per batch,head block) ---------------------------
__global__ __launch_bounds__(256) void attention_kernel(const float* __restrict__ qkv,
                                                        float* __restrict__ o) {
    extern __shared__ float sm[];         // kv: NF*DHD floats, sc: NF*64 floats
    float* kv = sm;
    float* sc = sm + NF * DHD;
    int b = blockIdx.x >> 2;
    int h = blockIdx.x & 3;
    int tid = threadIdx.x;
    int lane = tid & 31, w = tid >> 5;
    const float* base = qkv + (size_t)b * NF * GG + h * DHD;

    for (int idx = tid; idx < NF * DHD; idx += 256) {
        int t = idx >> 8, d = idx & 255;
        kv[idx] = base[(size_t)t * GG + HH + d];
    }
    __syncthreads();
    for (int i = w; i < NF; i += 8) {
        float q[8];
        const float* qp = base + (size_t)i * GG;
        #pragma unroll
        for (int c = 0; c < 8; c++) q[c] = qp[lane + 32 * c];
        for (int j = 0; j < NF; j++) {
            const float* kp = kv + j * DHD;
            float s = 0.f;
            #pragma unroll
            for (int c = 0; c < 8; c++) s += q[c] * kp[lane + 32 * c];
            #pragma unroll
            for (int off = 16; off; off >>= 1) s += __shfl_xor_sync(0xffffffffu, s, off);
            if (lane == 0) sc[i * 64 + j] = s * 0.0625f;   // 1/sqrt(256)
        }
    }
    __syncthreads();
    for (int i = w; i < NF; i += 8) {
        float v0 = (lane < NF) ? sc[i * 64 + lane] : -1e30f;
        float v1 = (lane + 32 < NF) ? sc[i * 64 + lane + 32] : -1e30f;
        float m = fmaxf(v0, v1);
        #pragma unroll
        for (int off = 16; off; off >>= 1) m = fmaxf(m, __shfl_xor_sync(0xffffffffu, m, off));
        float e0 = (lane < NF) ? expf(v0 - m) : 0.f;
        float e1 = (lane + 32 < NF) ? expf(v1 - m) : 0.f;
        float ss = e0 + e1;
        #pragma unroll
        for (int off = 16; off; off >>= 1) ss += __shfl_xor_sync(0xffffffffu, ss, off);
        float inv = 1.f / ss;
        if (lane < NF) sc[i * 64 + lane] = e0 * inv;
        if (lane + 32 < NF) sc[i * 64 + lane + 32] = e1 * inv;
    }
    __syncthreads();
    for (int idx = tid; idx < NF * DHD; idx += 256) {
        int t = idx >> 8, d = idx & 255;
        kv[idx] = base[(size_t)t * GG + 2 * HH + d];
    }
    __syncthreads();
    float acc[NF];
    #pragma unroll
    for (int i = 0; i < NF; i++) acc[i] = 0.f;
    int d = tid;
    for (int j = 0; j < NF; j++) {
        float vv = kv[j * DHD + d];
        #pragma unroll
        for (int i = 0; i < NF; i++) acc[i] += sc[i * 64 + j] * vv;
    }
    float* ob = o + (size_t)b * NF * HH + h * DHD + d;
    #pragma unroll
    for (int i = 0; i < NF; i++) ob[(size_t)i * HH] = acc[i];
}

__global__ void mean61_kernel(const float* __restrict__ o, float* __restrict__ obar) {
    int idx = blockIdx.x * 256 + threadIdx.x;
    if (idx >= BB * HH) return;
    int b = idx >> 10, c = idx & 1023;
    const float* p = o + (size_t)b * NF * HH + c;
    float s = 0.f;
    for (int t = 0; t < NF; t++) s += p[(size_t)t * HH];
    obar[idx] = s * (1.f / (float)NF);
}

// ---------------- GRU gate math ----------------------------------------------
__global__ void gru_gate(const float* __restrict__ gi, size_t gi_rs,
                         const float* __restrict__ gh,
                         float* __restrict__ h,
                         float* __restrict__ seqout, size_t seq_rs) {
    int idx = blockIdx.x * 256 + threadIdx.x;
    if (idx >= BB * HH) return;
    int b = idx >> 10, j = idx & 1023;
    const float* gib = gi + (size_t)b * gi_rs;
    const float* ghb = gh + (size_t)b * GG;
    float ir = gib[j],        hr = ghb[j];
    float iz = gib[HH + j],   hz = ghb[HH + j];
    float in = gib[2*HH + j], hn = ghb[2*HH + j];
    float r = 1.f / (1.f + expf(-(ir + hr)));
    float z = 1.f / (1.f + expf(-(iz + hz)));
    float n = tanhf(in + r * hn);
    float hp = h[idx];
    float hnew = (1.f - z) * n + z * hp;
    h[idx] = hnew;
    if (seqout) seqout[(size_t)b * seq_rs + j] = hnew;
}

// hid += mctx (elementwise)
__global__ void add_mctx_kernel(float* __restrict__ hid, const float* __restrict__ mctx) {
    int idx = blockIdx.x * 256 + threadIdx.x;
    if (idx >= BB * HH) return;
    hid[idx] += mctx[idx];
}

// ---------------- decode init: x0 and prev6d ---------------------------------
__global__ void init_decode(const float* __restrict__ inseq,
                            float* __restrict__ xt, float* __restrict__ p6) {
    int idx = blockIdx.x * 256 + threadIdx.x;
    if (idx >= BB * DD) return;
    int b = idx / DD, d = idx % DD;
    const float* last = inseq + ((size_t)b * TS + (TS - 1)) * DD;
    xt[idx] = last[d];
    if (d < NJ * 6) {
        int j = d / 6, o = d % 6;
        int src = (o < 3) ? (j * 9 + o * 3) : (j * 9 + (o - 3) * 3 + 1);
        p6[(size_t)b * 90 + d] = last[src];
    }
}

// ---------------- spl head layer2 + 6d accumulate + rot6d->rotmat ------------
__global__ __launch_bounds__(192) void spl2_rot(const float* __restrict__ z1,
                                                const float* __restrict__ w2,
                                                const float* __restrict__ b2,
                                                float* __restrict__ p6,
                                                float* __restrict__ xt,
                                                float* __restrict__ out, int step) {
    int bj = blockIdx.x;
    int b = bj / NJ, j = bj % NJ;
    int w = threadIdx.x >> 5, lane = threadIdx.x & 31;
    __shared__ float v6[6];
    const float* zz = z1 + (size_t)b * (NJ * 128) + j * 128;
    const float* ww = w2 + ((size_t)j * 6 + w) * 128;
    float s = 0.f;
    #pragma unroll
    for (int c = 0; c < 4; c++) s += zz[lane + 32 * c] * ww[lane + 32 * c];
    #pragma unroll
    for (int off = 16; off; off >>= 1) s += __shfl_xor_sync(0xffffffffu, s, off);
    if (lane == 0)
        v6[w] = p6[(size_t)b * 90 + j * 6 + w] + s + b2[j * 6 + w];
    __syncthreads();
    if (threadIdx.x < 6) {
        float v = v6[threadIdx.x];
        p6[(size_t)b * 90 + j * 6 + threadIdx.x] = v;
        out[((size_t)b * PREDN + step) * 90 + j * 6 + threadIdx.x] = v;
    }
    if (threadIdx.x == 0) {
        float a1x = v6[0], a2x = v6[1], a1y = v6[2], a2y = v6[3], a1z = v6[4], a2z = v6[5];
        float n1 = fmaxf(sqrtf(a1x*a1x + a1y*a1y + a1z*a1z), 1e-12f);
        float b1x = a1x / n1, b1y = a1y / n1, b1z = a1z / n1;
        float dot = b1x*a2x + b1y*a2y + b1z*a2z;
        float ox = a2x - dot*b1x, oy = a2y - dot*b1y, oz = a2z - dot*b1z;
        float n2 = fmaxf(sqrtf(ox*ox + oy*oy + oz*oz), 1e-12f);
        float b2x = ox / n2, b2y = oy / n2, b2z = oz / n2;
        float b3x = b1y*b2z - b1z*b2y;
        float b3y = b1z*b2x - b1x*b2z;
        float b3z = b1x*b2y - b1y*b2x;
        float* xo = xt + (size_t)b * DD + j * 9;
        xo[0] = b1x; xo[1] = b2x; xo[2] = b3x;
        xo[3] = b1y; xo[4] = b2y; xo[5] = b3y;
        xo[6] = b1z; xo[7] = b2z; xo[8] = b3z;
    }
}

// ---------------- host orchestration -----------------------------------------

static inline void gemm(const float* A, const float* W, const float* bias,
                        float* C, int M, int N, int K, int act) {
    dim3 g(N / 128, M / 128);
    gemm_bf16c<<<g, 256>>>(A, W, bias, C, M, N, K, act);
}

extern "C" void kernel_launch(void* const* d_in, const int* in_sizes, int n_in,
                              void* d_out, int out_size) {
    const float* poses      = (const float*)d_in[0];
    const float* freq_w     = (const float*)d_in[1];
    const float* freq_b     = (const float*)d_in[2];
    const float* attn_in_w  = (const float*)d_in[3];
    const float* attn_in_b  = (const float*)d_in[4];
    const float* attn_out_w = (const float*)d_in[5];
    const float* attn_out_b = (const float*)d_in[6];
    const float* gru_wih0   = (const float*)d_in[7];
    const float* gru_whh0   = (const float*)d_in[8];
    const float* gru_bih0   = (const float*)d_in[9];
    const float* gru_bhh0   = (const float*)d_in[10];
    const float* gru_wih1   = (const float*)d_in[11];
    const float* gru_whh1   = (const float*)d_in[12];
    const float* gru_bih1   = (const float*)d_in[13];
    const float* gru_bhh1   = (const float*)d_in[14];
    const float* pre_w      = (const float*)d_in[15];
    const float* pre_b      = (const float*)d_in[16];
    const float* spl_w1     = (const float*)d_in[17];   // (15,128,1024) == (1920,1024)
    const float* spl_b1     = (const float*)d_in[18];   // (1920)
    const float* spl_w2     = (const float*)d_in[19];
    const float* spl_b2     = (const float*)d_in[20];
    float* out = (float*)d_out;

    float *pBig, *pSeq, *pIn, *pFrq, *pCos, *pObar, *pMctx, *pH0, *pH1, *pGh, *pGx,
          *pHid, *pZ1, *pXt, *pP6;
    cudaGetSymbolAddress((void**)&pBig, g_big);
    cudaGetSymbolAddress((void**)&pSeq, g_seq);
    cudaGetSymbolAddress((void**)&pIn,  g_in);
    cudaGetSymbolAddress((void**)&pFrq, g_frq);
    cudaGetSymbolAddress((void**)&pCos, g_cosm);
    cudaGetSymbolAddress((void**)&pObar, g_obar);
    cudaGetSymbolAddress((void**)&pMctx, g_mctx);
    cudaGetSymbolAddress((void**)&pH0, g_h0);
    cudaGetSymbolAddress((void**)&pH1, g_h1);
    cudaGetSymbolAddress((void**)&pGh, g_gh);
    cudaGetSymbolAddress((void**)&pGx, g_gx);
    cudaGetSymbolAddress((void**)&pHid, g_hid);
    cudaGetSymbolAddress((void**)&pZ1, g_z1);
    cudaGetSymbolAddress((void**)&pXt, g_xt);
    cudaGetSymbolAddress((void**)&pP6, g_p6);

    float* qkv   = pBig;                              // (B*NF, 3072)
    float* attno = pBig + (size_t)BB * NF * GG;       // (B*NF, 1024)
    float* gi    = pBig;                              // (B*TS, 3072)
    float* feat  = pSeq;                              // (B*NF, 1024)
    float* seq0  = pSeq;                              // (B*TS, 1024)

    const int BF = BB * NF;   // 15616 = 122*128
    const int BT = BB * TS;   // 30720 = 240*128

    // ---- frequency attention branch ----
    copy_inseq_kernel<<<(BB*TS*DD + 255) / 256, 256>>>(poses, pIn);
    build_cos_kernel<<<(NF*TS + 255) / 256, 256>>>(pCos);
    freq_kernel<<<dim3(BB, NF), 160>>>(pIn, pCos, pFrq);
    gemm(pFrq, freq_w, freq_b, feat, BF, HH, DD, 0);
    gemm(feat, attn_in_w, attn_in_b, qkv, BF, GG, HH, 0);

    int smem_attn = (NF * DHD + NF * 64) * (int)sizeof(float);   // 78080 B
    cudaFuncSetAttribute(attention_kernel, cudaFuncAttributeMaxDynamicSharedMemorySize, smem_attn);
    attention_kernel<<<BB * NHEAD, 256, smem_attn>>>(qkv, attno);
    mean61_kernel<<<(BB*HH + 255) / 256, 256>>>(attno, pObar);
    gemm(pObar, attn_out_w, attn_out_b, pMctx, BB, HH, HH, 0);

    // ---- GRU layer 0 ----
    gemm(pIn, gru_wih0, gru_bih0, gi, BT, GG, DD, 0);
    cudaMemsetAsync(pH0, 0, (size_t)BB * HH * sizeof(float));
    for (int t = 0; t < TS; t++) {
        gemm(pH0, gru_whh0, gru_bhh0, pGh, BB, GG, HH, 0);
        gru_gate<<<(BB*HH)/256, 256>>>(gi + (size_t)t * GG, (size_t)TS * GG,
                                       pGh, pH0, seq0 + (size_t)t * HH, (size_t)TS * HH);
    }

    // ---- GRU layer 1 ----
    gemm(seq0, gru_wih1, gru_bih1, gi, BT, GG, HH, 0);
    cudaMemsetAsync(pH1, 0, (size_t)BB * HH * sizeof(float));
    for (int t = 0; t < TS; t++) {
        gemm(pH1, gru_whh1, gru_bhh1, pGh, BB, GG, HH, 0);
        gru_gate<<<(BB*HH)/256, 256>>>(gi + (size_t)t * GG, (size_t)TS * GG,
                                       pGh, pH1, nullptr, 0);
    }

    // ---- autoregressive decode ----
    init_decode<<<(BB*DD + 255) / 256, 256>>>(pIn, pXt, pP6);
    for (int s = 0; s < PREDN; s++) {
        gemm(pXt, gru_wih0, gru_bih0, pGx, BB, GG, DD, 0);
        gemm(pH0, gru_whh0, gru_bhh0, pGh, BB, GG, HH, 0);
        gru_gate<<<(BB*HH)/256, 256>>>(pGx, (size_t)GG, pGh, pH0, nullptr, 0);

        gemm(pH0, gru_wih1, gru_bih1, pGx, BB, GG, HH, 0);
        gemm(pH1, gru_whh1, gru_bhh1, pGh, BB, GG, HH, 0);
        gru_gate<<<(BB*HH)/256, 256>>>(pGx, (size_t)GG, pGh, pH1, nullptr, 0);

        gemm(pH1, pre_w, pre_b, pHid, BB, HH, HH, 1);            // relu
        add_mctx_kernel<<<(BB*HH)/256, 256>>>(pHid, pMctx);      // + motion_ctx
        gemm(pHid, spl_w1, spl_b1, pZ1, BB, NJ * 128, HH, 1);    // relu
        spl2_rot<<<BB * NJ, 192>>>(pZ1, spl_w2, spl_b2, pP6, pXt, out, s);
    }
}

// round 4
// speedup vs baseline: 2.3439x; 2.1554x over previous
#include <cuda_runtime.h>
#include <cuda_bf16.h>
#include <mma.h>
#include <math.h>

using namespace nvcuda;

#define BB    256
#define TS    120
#define PREDN 24
#define NJ    15
#define HH    1024
#define DD    135
#define NF    61        // rfft length = TS/2+1
#define GG    3072      // 3*H
#define NHEAD 4
#define DHD   256       // H / NHEAD

// padded K (bias column appended, rounded to 32)
#define KP1024 1056
#define KP135  160

// ---------------- weight split pools (bf16 hi/lo) ----------------------------
// offsets in elements
#define OFF_ATTNIN  0ull
#define OFF_WIH0    3244032ull
#define OFF_WHH0    3735552ull
#define OFF_WIH1    6979584ull
#define OFF_WHH1    10223616ull
#define OFF_FREQ    13467648ull
#define OFF_ATTNOUT 13631488ull
#define OFF_PRE     14712832ull
#define OFF_SPL1    15794176ull
#define WPOOL_TOTAL 17821696ull

__device__ __nv_bfloat16 g_whi[WPOOL_TOTAL];
__device__ __nv_bfloat16 g_wlo[WPOOL_TOTAL];

// ---------------- scratch buffers (static device globals; no allocation) ----
__device__ float g_big[(size_t)BB * TS * GG];         // gi / qkv / attn-out (aliased)
__device__ float g_seq[(size_t)BB * TS * HH];         // seq0 / feat (aliased)
__device__ float g_in [(size_t)BB * TS * DD];
__device__ float g_frq[(size_t)BB * NF * DD];
__device__ float g_cosm[NF * TS];
__device__ float g_obar[BB * HH];
__device__ float g_mctx[BB * HH];
__device__ float g_h0[BB * HH];
__device__ float g_h1[BB * HH];
__device__ float g_ghp[(size_t)4 * BB * GG];          // split-K partials (gh)
__device__ float g_gxp[(size_t)4 * BB * GG];          // split-K partials (gx)
__device__ float g_prep[(size_t)8 * BB * HH];         // split-K partials (pre)
__device__ float g_splp[(size_t)8 * BB * NJ * 128];   // split-K partials (spl1)
__device__ float g_hid[BB * HH];
__device__ float g_z1[BB * NJ * 128];
__device__ float g_xt[BB * DD];
__device__ float g_p6[BB * NJ * 6];

// ---------------- small utility kernels -------------------------------------

__global__ void copy_inseq_kernel(const float* __restrict__ poses, float* __restrict__ dst) {
    int idx = blockIdx.x * 256 + threadIdx.x;
    if (idx >= BB * TS * DD) return;
    int d = idx % DD;
    int t = (idx / DD) % TS;
    int b = idx / (TS * DD);
    dst[idx] = poses[((size_t)b * (TS + PREDN) + t) * DD + d];
}

__global__ void build_cos_kernel(float* __restrict__ cosm) {
    int idx = blockIdx.x * 256 + threadIdx.x;
    if (idx >= NF * TS) return;
    int f = idx / TS, t = idx % TS;
    cosm[idx] = (float)cos(2.0 * 3.14159265358979323846 * (double)(f * t) / (double)TS);
}

// freq[b,f,d] = sum_t cos[f,t] * inseq[b,t,d]
__global__ void freq_kernel(const float* __restrict__ inseq, const float* __restrict__ cosm,
                            float* __restrict__ freq) {
    int b = blockIdx.x, f = blockIdx.y, d = threadIdx.x;
    if (d >= DD) return;
    const float* xp = inseq + (size_t)b * TS * DD + d;
    const float* cp = cosm + f * TS;
    float s = 0.f;
    #pragma unroll 4
    for (int t = 0; t < TS; t++) s += cp[t] * xp[(size_t)t * DD];
    freq[((size_t)b * NF + f) * DD + d] = s;
}

// ---------------- weight splitter: fp32 (N,K)+bias -> bf16 hi/lo (N,KP) ------
__global__ void split_w_kernel(const float* __restrict__ W, const float* __restrict__ bias,
                               __nv_bfloat16* __restrict__ hi, __nv_bfloat16* __restrict__ lo,
                               int N, int K, int KP) {
    size_t idx = (size_t)blockIdx.x * 256 + threadIdx.x;
    if (idx >= (size_t)N * KP) return;
    int n = (int)(idx / KP), k = (int)(idx % KP);
    float v = 0.f;
    if (k < K) v = W[(size_t)n * K + k];
    else if (k == K) v = bias[n];
    __nv_bfloat16 h = __float2bfloat16(v);
    hi[idx] = h;
    lo[idx] = __float2bfloat16(v - __bfloat162float(h));
}

// ---------------- error-compensated bf16 GEMM v2 -----------------------------
// C = act(A(MxK,fp32) * Wsplit(NxKP,bf16 hi/lo)^T), bias embedded in W col K.
// Split-K via gridDim.z: slice z writes C + z*M*N (act must be 0 when z>1).
// Requires M % 128 == 0, N % 128 == 0, KP % 32 == 0.
__global__ __launch_bounds__(256, 2) void gemm2_kernel(
    const float* __restrict__ A, const __nv_bfloat16* __restrict__ Whi,
    const __nv_bfloat16* __restrict__ Wlo, float* __restrict__ C,
    int M, int N, int K, int KP, int act)
{
    __shared__ __align__(16) __nv_bfloat16 AsH[128][40];
    __shared__ __align__(16) __nv_bfloat16 AsL[128][40];
    __shared__ __align__(16) __nv_bfloat16 WsH[128][40];
    __shared__ __align__(16) __nv_bfloat16 WsL[128][40];

    int tid = threadIdx.x;
    int warp = tid >> 5;
    int wm = warp >> 1, wn = warp & 1;     // 4x2 warp grid, warp tile 32x64
    int m0 = blockIdx.y * 128, n0 = blockIdx.x * 128;

    wmma::fragment<wmma::accumulator, 16, 16, 16, float> acc[2][4];
    #pragma unroll
    for (int i = 0; i < 2; i++)
        #pragma unroll
        for (int j = 0; j < 4; j++)
            wmma::fill_fragment(acc[i][j], 0.0f);

    int col  = tid & 31;
    int row0 = tid >> 5;

    int CH  = KP >> 5;                         // total 32-wide chunks
    int cpz = (CH + gridDim.z - 1) / gridDim.z;
    int c0  = blockIdx.z * cpz;
    int c1  = c0 + cpz; if (c1 > CH) c1 = CH;

    for (int c = c0; c < c1; c++) {
        int k0 = c << 5;
        // ---- A: fp32 load + split to hi/lo ----
        if (k0 + 32 <= K) {
            #pragma unroll
            for (int i = 0; i < 16; i++) {
                int r = row0 + i * 8;
                float va = A[(size_t)(m0 + r) * K + k0 + col];
                __nv_bfloat16 ah = __float2bfloat16(va);
                AsH[r][col] = ah;
                AsL[r][col] = __float2bfloat16(va - __bfloat162float(ah));
            }
        } else {
            int gk = k0 + col;
            #pragma unroll
            for (int i = 0; i < 16; i++) {
                int r = row0 + i * 8;
                float va = (gk < K) ? A[(size_t)(m0 + r) * K + gk]
                                    : (gk == K ? 1.0f : 0.0f);
                __nv_bfloat16 ah = __float2bfloat16(va);
                AsH[r][col] = ah;
                AsL[r][col] = __float2bfloat16(va - __bfloat162float(ah));
            }
        }
        // ---- W: pre-split bf16, vectorized 8B loads ----
        #pragma unroll
        for (int it = 0; it < 4; it++) {
            int slot = tid + it * 256;          // 0..1023
            int rw = slot >> 3;                 // 0..127
            int cg = (slot & 7) << 2;           // 0,4,...,28
            size_t goff = (size_t)(n0 + rw) * KP + k0 + cg;
            *(uint2*)&WsH[rw][cg] = *(const uint2*)(Whi + goff);
            *(uint2*)&WsL[rw][cg] = *(const uint2*)(Wlo + goff);
        }
        __syncthreads();
        #pragma unroll
        for (int kk = 0; kk < 32; kk += 16) {
            wmma::fragment<wmma::matrix_a, 16, 16, 16, __nv_bfloat16, wmma::row_major> faH[2], faL[2];
            #pragma unroll
            for (int i = 0; i < 2; i++) {
                wmma::load_matrix_sync(faH[i], &AsH[wm * 32 + i * 16][kk], 40);
                wmma::load_matrix_sync(faL[i], &AsL[wm * 32 + i * 16][kk], 40);
            }
            #pragma unroll
            for (int j = 0; j < 4; j++) {
                wmma::fragment<wmma::matrix_b, 16, 16, 16, __nv_bfloat16, wmma::col_major> fbH, fbL;
                wmma::load_matrix_sync(fbH, &WsH[wn * 64 + j * 16][kk], 40);
                wmma::load_matrix_sync(fbL, &WsL[wn * 64 + j * 16][kk], 40);
                #pragma unroll
                for (int i = 0; i < 2; i++) {
                    wmma::mma_sync(acc[i][j], faH[i], fbH, acc[i][j]);
                    wmma::mma_sync(acc[i][j], faH[i], fbL, acc[i][j]);
                    wmma::mma_sync(acc[i][j], faL[i], fbH, acc[i][j]);
                }
            }
        }
        __syncthreads();
    }

    float* Cz = C + (size_t)blockIdx.z * M * N;
    #pragma unroll
    for (int i = 0; i < 2; i++) {
        #pragma unroll
        for (int j = 0; j < 4; j++) {
            if (act == 1) {
                #pragma unroll
                for (int e = 0; e < acc[i][j].num_elements; e++)
                    acc[i][j].x[e] = fmaxf(acc[i][j].x[e], 0.0f);
            }
            wmma::store_matrix_sync(
                Cz + (size_t)(m0 + wm * 32 + i * 16) * N + (n0 + wn * 64 + j * 16),
                acc[i][j], N, wmma::mem_row_major);
        }
    }
}

// ---------------- attention (per batch,head block) ---------------------------
__global__ __launch_bounds__(256) void attention_kernel(const float* __restrict__ qkv,
                                                        float* __restrict__ o) {
    extern __shared__ float sm[];         // kv: NF*DHD floats, sc: NF*64 floats
    float* kv = sm;
    float* sc = sm + NF * DHD;
    int b = blockIdx.x >> 2;
    int h = blockIdx.x & 3;
    int tid = threadIdx.x;
    int lane = tid & 31, w = tid >> 5;
    const float* base = qkv + (size_t)b * NF * GG + h * DHD;

    for (int idx = tid; idx < NF * DHD; idx += 256) {
        int t = idx >> 8, d = idx & 255;
        kv[idx] = base[(size_t)t * GG + HH + d];
    }
    __syncthreads();
    for (int i = w; i < NF; i += 8) {
        float q[8];
        const float* qp = base + (size_t)i * GG;
        #pragma unroll
        for (int c = 0; c < 8; c++) q[c] = qp[lane + 32 * c];
        for (int j = 0; j < NF; j++) {
            const float* kp = kv + j * DHD;
            float s = 0.f;
            #pragma unroll
            for (int c = 0; c < 8; c++) s += q[c] * kp[lane + 32 * c];
            #pragma unroll
            for (int off = 16; off; off >>= 1) s += __shfl_xor_sync(0xffffffffu, s, off);
            if (lane == 0) sc[i * 64 + j] = s * 0.0625f;   // 1/sqrt(256)
        }
    }
    __syncthreads();
    for (int i = w; i < NF; i += 8) {
        float v0 = (lane < NF) ? sc[i * 64 + lane] : -1e30f;
        float v1 = (lane + 32 < NF) ? sc[i * 64 + lane + 32] : -1e30f;
        float m = fmaxf(v0, v1);
        #pragma unroll
        for (int off = 16; off; off >>= 1) m = fmaxf(m, __shfl_xor_sync(0xffffffffu, m, off));
        float e0 = (lane < NF) ? expf(v0 - m) : 0.f;
        float e1 = (lane + 32 < NF) ? expf(v1 - m) : 0.f;
        float ss = e0 + e1;
        #pragma unroll
        for (int off = 16; off; off >>= 1) ss += __shfl_xor_sync(0xffffffffu, ss, off);
        float inv = 1.f / ss;
        if (lane < NF) sc[i * 64 + lane] = e0 * inv;
        if (lane + 32 < NF) sc[i * 64 + lane + 32] = e1 * inv;
    }
    __syncthreads();
    for (int idx = tid; idx < NF * DHD; idx += 256) {
        int t = idx >> 8, d = idx & 255;
        kv[idx] = base[(size_t)t * GG + 2 * HH + d];
    }
    __syncthreads();
    float acc[NF];
    #pragma unroll
    for (int i = 0; i < NF; i++) acc[i] = 0.f;
    int d = tid;
    for (int j = 0; j < NF; j++) {
        float vv = kv[j * DHD + d];
        #pragma unroll
        for (int i = 0; i < NF; i++) acc[i] += sc[i * 64 + j] * vv;
    }
    float* ob = o + (size_t)b * NF * HH + h * DHD + d;
    #pragma unroll
    for (int i = 0; i < NF; i++) ob[(size_t)i * HH] = acc[i];
}

__global__ void mean61_kernel(const float* __restrict__ o, float* __restrict__ obar) {
    int idx = blockIdx.x * 256 + threadIdx.x;
    if (idx >= BB * HH) return;
    int b = idx >> 10, c = idx & 1023;
    const float* p = o + (size_t)b * NF * HH + c;
    float s = 0.f;
    for (int t = 0; t < NF; t++) s += p[(size_t)t * HH];
    obar[idx] = s * (1.f / (float)NF);
}

// ---------------- GRU gate math (split-K aware) -------------------------------
__global__ void gru_gate2(const float* __restrict__ gi, size_t gi_rs, int gi_sk, size_t gi_ss,
                          const float* __restrict__ ghp, int gh_sk,
                          float* __restrict__ h,
                          float* __restrict__ seqout, size_t seq_rs) {
    int idx = blockIdx.x * 256 + threadIdx.x;
    if (idx >= BB * HH) return;
    int b = idx >> 10, j = idx & 1023;
    float ir = 0.f, iz = 0.f, in = 0.f;
    for (int s = 0; s < gi_sk; s++) {
        const float* g = gi + (size_t)s * gi_ss + (size_t)b * gi_rs;
        ir += g[j]; iz += g[HH + j]; in += g[2 * HH + j];
    }
    float hr = 0.f, hz = 0.f, hn = 0.f;
    for (int s = 0; s < gh_sk; s++) {
        const float* g = ghp + (size_t)s * (BB * GG) + (size_t)b * GG;
        hr += g[j]; hz += g[HH + j]; hn += g[2 * HH + j];
    }
    float r = 1.f / (1.f + expf(-(ir + hr)));
    float z = 1.f / (1.f + expf(-(iz + hz)));
    float n = tanhf(in + r * hn);
    float hp = h[idx];
    float hnew = (1.f - z) * n + z * hp;
    h[idx] = hnew;
    if (seqout) seqout[(size_t)b * seq_rs + j] = hnew;
}

// ---------------- split-K partial reduction (+relu, +addend) -----------------
__global__ void reduce_act_kernel(const float* __restrict__ part, int sk, int mn,
                                  const float* __restrict__ addend,
                                  float* __restrict__ out, int act) {
    int idx = blockIdx.x * 256 + threadIdx.x;
    if (idx >= mn) return;
    float s = 0.f;
    for (int i = 0; i < sk; i++) s += part[(size_t)i * mn + idx];
    if (act) s = fmaxf(s, 0.f);
    if (addend) s += addend[idx];
    out[idx] = s;
}

// ---------------- decode init: x0 and prev6d ---------------------------------
__global__ void init_decode(const float* __restrict__ inseq,
                            float* __restrict__ xt, float* __restrict__ p6) {
    int idx = blockIdx.x * 256 + threadIdx.x;
    if (idx >= BB * DD) return;
    int b = idx / DD, d = idx % DD;
    const float* last = inseq + ((size_t)b * TS + (TS - 1)) * DD;
    xt[idx] = last[d];
    if (d < NJ * 6) {
        int j = d / 6, o = d % 6;
        int src = (o < 3) ? (j * 9 + o * 3) : (j * 9 + (o - 3) * 3 + 1);
        p6[(size_t)b * 90 + d] = last[src];
    }
}

// ---------------- spl head layer2 + 6d accumulate + rot6d->rotmat ------------
__global__ __launch_bounds__(192) void spl2_rot(const float* __restrict__ z1,
                                                const float* __restrict__ w2,
                                                const float* __restrict__ b2,
                                                float* __restrict__ p6,
                                                float* __restrict__ xt,
                                                float* __restrict__ out, int step) {
    int bj = blockIdx.x;
    int b = bj / NJ, j = bj % NJ;
    int w = threadIdx.x >> 5, lane = threadIdx.x & 31;
    __shared__ float v6[6];
    const float* zz = z1 + (size_t)b * (NJ * 128) + j * 128;
    const float* ww = w2 + ((size_t)j * 6 + w) * 128;
    float s = 0.f;
    #pragma unroll
    for (int c = 0; c < 4; c++) s += zz[lane + 32 * c] * ww[lane + 32 * c];
    #pragma unroll
    for (int off = 16; off; off >>= 1) s += __shfl_xor_sync(0xffffffffu, s, off);
    if (lane == 0)
        v6[w] = p6[(size_t)b * 90 + j * 6 + w] + s + b2[j * 6 + w];
    __syncthreads();
    if (threadIdx.x < 6) {
        float v = v6[threadIdx.x];
        p6[(size_t)b * 90 + j * 6 + threadIdx.x] = v;
        out[((size_t)b * PREDN + step) * 90 + j * 6 + threadIdx.x] = v;
    }
    if (threadIdx.x == 0) {
        float a1x = v6[0], a2x = v6[1], a1y = v6[2], a2y = v6[3], a1z = v6[4], a2z = v6[5];
        float n1 = fmaxf(sqrtf(a1x*a1x + a1y*a1y + a1z*a1z), 1e-12f);
        float b1x = a1x / n1, b1y = a1y / n1, b1z = a1z / n1;
        float dot = b1x*a2x + b1y*a2y + b1z*a2z;
        float ox = a2x - dot*b1x, oy = a2y - dot*b1y, oz = a2z - dot*b1z;
        float n2 = fmaxf(sqrtf(ox*ox + oy*oy + oz*oz), 1e-12f);
        float b2x = ox / n2, b2y = oy / n2, b2z = oz / n2;
        float b3x = b1y*b2z - b1z*b2y;
        float b3y = b1z*b2x - b1x*b2z;
        float b3z = b1x*b2y - b1y*b2x;
        float* xo = xt + (size_t)b * DD + j * 9;
        xo[0] = b1x; xo[1] = b2x; xo[2] = b3x;
        xo[3] = b1y; xo[4] = b2y; xo[5] = b3y;
        xo[6] = b1z; xo[7] = b2z; xo[8] = b3z;
    }
}

// ---------------- host orchestration -----------------------------------------

static inline void gemm2(const float* A, const __nv_bfloat16* whi, const __nv_bfloat16* wlo,
                         float* C, int M, int N, int K, int KP, int act, int sk) {
    dim3 g(N / 128, M / 128, sk);
    gemm2_kernel<<<g, 256>>>(A, whi, wlo, C, M, N, K, KP, act);
}

static inline void splitw(const float* W, const float* bias,
                          __nv_bfloat16* hi, __nv_bfloat16* lo, int N, int K, int KP) {
    size_t n = (size_t)N * KP;
    split_w_kernel<<<(int)((n + 255) / 256), 256>>>(W, bias, hi, lo, N, K, KP);
}

extern "C" void kernel_launch(void* const* d_in, const int* in_sizes, int n_in,
                              void* d_out, int out_size) {
    const float* poses      = (const float*)d_in[0];
    const float* freq_w     = (const float*)d_in[1];
    const float* freq_b     = (const float*)d_in[2];
    const float* attn_in_w  = (const float*)d_in[3];
    const float* attn_in_b  = (const float*)d_in[4];
    const float* attn_out_w = (const float*)d_in[5];
    const float* attn_out_b = (const float*)d_in[6];
    const float* gru_wih0   = (const float*)d_in[7];
    const float* gru_whh0   = (const float*)d_in[8];
    const float* gru_bih0   = (const float*)d_in[9];
    const float* gru_bhh0   = (const float*)d_in[10];
    const float* gru_wih1   = (const float*)d_in[11];
    const float* gru_whh1   = (const float*)d_in[12];
    const float* gru_bih1   = (const float*)d_in[13];
    const float* gru_bhh1   = (const float*)d_in[14];
    const float* pre_w      = (const float*)d_in[15];
    const float* pre_b      = (const float*)d_in[16];
    const float* spl_w1     = (const float*)d_in[17];   // (15,128,1024) == (1920,1024)
    const float* spl_b1     = (const float*)d_in[18];   // (1920)
    const float* spl_w2     = (const float*)d_in[19];
    const float* spl_b2     = (const float*)d_in[20];
    float* out = (float*)d_out;

    float *pBig, *pSeq, *pIn, *pFrq, *pCos, *pObar, *pMctx, *pH0, *pH1,
          *pGhp, *pGxp, *pPrep, *pSplp, *pHid, *pZ1, *pXt, *pP6;
    __nv_bfloat16 *pWhi, *pWlo;
    cudaGetSymbolAddress((void**)&pBig, g_big);
    cudaGetSymbolAddress((void**)&pSeq, g_seq);
    cudaGetSymbolAddress((void**)&pIn,  g_in);
    cudaGetSymbolAddress((void**)&pFrq, g_frq);
    cudaGetSymbolAddress((void**)&pCos, g_cosm);
    cudaGetSymbolAddress((void**)&pObar, g_obar);
    cudaGetSymbolAddress((void**)&pMctx, g_mctx);
    cudaGetSymbolAddress((void**)&pH0, g_h0);
    cudaGetSymbolAddress((void**)&pH1, g_h1);
    cudaGetSymbolAddress((void**)&pGhp, g_ghp);
    cudaGetSymbolAddress((void**)&pGxp, g_gxp);
    cudaGetSymbolAddress((void**)&pPrep, g_prep);
    cudaGetSymbolAddress((void**)&pSplp, g_splp);
    cudaGetSymbolAddress((void**)&pHid, g_hid);
    cudaGetSymbolAddress((void**)&pZ1, g_z1);
    cudaGetSymbolAddress((void**)&pXt, g_xt);
    cudaGetSymbolAddress((void**)&pP6, g_p6);
    cudaGetSymbolAddress((void**)&pWhi, g_whi);
    cudaGetSymbolAddress((void**)&pWlo, g_wlo);

    float* qkv   = pBig;                              // (B*NF, 3072)
    float* attno = pBig + (size_t)BB * NF * GG;       // (B*NF, 1024)
    float* gi    = pBig;                              // (B*TS, 3072)
    float* feat  = pSeq;                              // (B*NF, 1024)
    float* seq0  = pSeq;                              // (B*TS, 1024)

    const int BF = BB * NF;   // 15616 = 122*128
    const int BT = BB * TS;   // 30720 = 240*128

    // ---- one-time weight splits ----
    splitw(attn_in_w, attn_in_b, pWhi + OFF_ATTNIN,  pWlo + OFF_ATTNIN,  GG, HH, KP1024);
    splitw(gru_wih0,  gru_bih0,  pWhi + OFF_WIH0,    pWlo + OFF_WIH0,    GG, DD, KP135);
    splitw(gru_whh0,  gru_bhh0,  pWhi + OFF_WHH0,    pWlo + OFF_WHH0,    GG, HH, KP1024);
    splitw(gru_wih1,  gru_bih1,  pWhi + OFF_WIH1,    pWlo + OFF_WIH1,    GG, HH, KP1024);
    splitw(gru_whh1,  gru_bhh1,  pWhi + OFF_WHH1,    pWlo + OFF_WHH1,    GG, HH, KP1024);
    splitw(freq_w,    freq_b,    pWhi + OFF_FREQ,    pWlo + OFF_FREQ,    HH, DD, KP135);
    splitw(attn_out_w,attn_out_b,pWhi + OFF_ATTNOUT, pWlo + OFF_ATTNOUT, HH, HH, KP1024);
    splitw(pre_w,     pre_b,     pWhi + OFF_PRE,     pWlo + OFF_PRE,     HH, HH, KP1024);
    splitw(spl_w1,    spl_b1,    pWhi + OFF_SPL1,    pWlo + OFF_SPL1,    NJ*128, HH, KP1024);

    // ---- frequency attention branch ----
    copy_inseq_kernel<<<(BB*TS*DD + 255) / 256, 256>>>(poses, pIn);
    build_cos_kernel<<<(NF*TS + 255) / 256, 256>>>(pCos);
    freq_kernel<<<dim3(BB, NF), 160>>>(pIn, pCos, pFrq);
    gemm2(pFrq, pWhi + OFF_FREQ, pWlo + OFF_FREQ, feat, BF, HH, DD, KP135, 0, 1);
    gemm2(feat, pWhi + OFF_ATTNIN, pWlo + OFF_ATTNIN, qkv, BF, GG, HH, KP1024, 0, 1);

    int smem_attn = (NF * DHD + NF * 64) * (int)sizeof(float);   // 78080 B
    cudaFuncSetAttribute(attention_kernel, cudaFuncAttributeMaxDynamicSharedMemorySize, smem_attn);
    attention_kernel<<<BB * NHEAD, 256, smem_attn>>>(qkv, attno);
    mean61_kernel<<<(BB*HH + 255) / 256, 256>>>(attno, pObar);
    gemm2(pObar, pWhi + OFF_ATTNOUT, pWlo + OFF_ATTNOUT, pMctx, BB, HH, HH, KP1024, 0, 1);

    // ---- GRU layer 0 ----
    gemm2(pIn, pWhi + OFF_WIH0, pWlo + OFF_WIH0, gi, BT, GG, DD, KP135, 0, 1);
    cudaMemsetAsync(pH0, 0, (size_t)BB * HH * sizeof(float));
    for (int t = 0; t < TS; t++) {
        gemm2(pH0, pWhi + OFF_WHH0, pWlo + OFF_WHH0, pGhp, BB, GG, HH, KP1024, 0, 4);
        gru_gate2<<<(BB*HH)/256, 256>>>(gi + (size_t)t * GG, (size_t)TS * GG, 1, 0,
                                        pGhp, 4, pH0, seq0 + (size_t)t * HH, (size_t)TS * HH);
    }

    // ---- GRU layer 1 ----
    gemm2(seq0, pWhi + OFF_WIH1, pWlo + OFF_WIH1, gi, BT, GG, HH, KP1024, 0, 1);
    cudaMemsetAsync(pH1, 0, (size_t)BB * HH * sizeof(float));
    for (int t = 0; t < TS; t++) {
        gemm2(pH1, pWhi + OFF_WHH1, pWlo + OFF_WHH1, pGhp, BB, GG, HH, KP1024, 0, 4);
        gru_gate2<<<(BB*HH)/256, 256>>>(gi + (size_t)t * GG, (size_t)TS * GG, 1, 0,
                                        pGhp, 4, pH1, nullptr, 0);
    }

    // ---- autoregressive decode ----
    init_decode<<<(BB*DD + 255) / 256, 256>>>(pIn, pXt, pP6);
    for (int s = 0; s < PREDN; s++) {
        gemm2(pXt, pWhi + OFF_WIH0, pWlo + OFF_WIH0, pGxp, BB, GG, DD, KP135, 0, 2);
        gemm2(pH0, pWhi + OFF_WHH0, pWlo + OFF_WHH0, pGhp, BB, GG, HH, KP1024, 0, 4);
        gru_gate2<<<(BB*HH)/256, 256>>>(pGxp, GG, 2, (size_t)BB * GG,
                                        pGhp, 4, pH0, nullptr, 0);

        gemm2(pH0, pWhi + OFF_WIH1, pWlo + OFF_WIH1, pGxp, BB, GG, HH, KP1024, 0, 4);
        gemm2(pH1, pWhi + OFF_WHH1, pWlo + OFF_WHH1, pGhp, BB, GG, HH, KP1024, 0, 4);
        gru_gate2<<<(BB*HH)/256, 256>>>(pGxp, GG, 4, (size_t)BB * GG,
                                        pGhp, 4, pH1, nullptr, 0);

        gemm2(pH1, pWhi + OFF_PRE, pWlo + OFF_PRE, pPrep, BB, HH, HH, KP1024, 0, 8);
        reduce_act_kernel<<<(BB*HH + 255)/256, 256>>>(pPrep, 8, BB*HH, pMctx, pHid, 1);

        gemm2(pHid, pWhi + OFF_SPL1, pWlo + OFF_SPL1, pSplp, BB, NJ*128, HH, KP1024, 0, 8);
        reduce_act_kernel<<<(BB*NJ*128 + 255)/256, 256>>>(pSplp, 8, BB*NJ*128, nullptr, pZ1, 1);

        spl2_rot<<<BB * NJ, 192>>>(pZ1, spl_w2, spl_b2, pP6, pXt, out, s);
    }
}

// round 5
// speedup vs baseline: 2.4064x; 1.0267x over previous
#include <cuda_runtime.h>
#include <cuda_bf16.h>
#include <mma.h>
#include <math.h>

using namespace nvcuda;

#define BB    256
#define TS    120
#define PREDN 24
#define NJ    15
#define HH    1024
#define DD    135
#define NF    61        // rfft length = TS/2+1
#define GG    3072      // 3*H
#define NHEAD 4
#define DHD   256       // H / NHEAD

// padded K (bias column appended, rounded to 32)
#define KP1024 1056
#define KP135  160

#define NBLK  144       // persistent grid size (<= 148 SMs -> co-resident)

// ---------------- weight split pools (bf16 hi/lo) ----------------------------
#define OFF_ATTNIN  0ull
#define OFF_WIH0    3244032ull
#define OFF_WHH0    3735552ull
#define OFF_WIH1    6979584ull
#define OFF_WHH1    10223616ull
#define OFF_FREQ    13467648ull
#define OFF_ATTNOUT 13631488ull
#define OFF_PRE     14712832ull
#define OFF_SPL1    15794176ull
#define WPOOL_TOTAL 17821696ull

__device__ __nv_bfloat16 g_whi[WPOOL_TOTAL];
__device__ __nv_bfloat16 g_wlo[WPOOL_TOTAL];

// ---------------- scratch buffers ---------------------------------------------
__device__ float g_big[(size_t)BB * TS * GG];         // gi / qkv / attn-out (aliased)
__device__ float g_seq[(size_t)BB * TS * HH];         // seq0 / feat (aliased)
__device__ float g_in [(size_t)BB * TS * DD];
__device__ float g_frq[(size_t)BB * NF * DD];
__device__ float g_cosm[NF * TS];
__device__ float g_obar[BB * HH];
__device__ float g_mctx[BB * HH];
__device__ float g_h0[BB * HH];
__device__ float g_h1[BB * HH];
__device__ float g_ghp[(size_t)4 * BB * GG];          // partials (gh / persistent)
__device__ float g_gxp[(size_t)4 * BB * GG];          // partials (gx)
__device__ float g_prep[(size_t)8 * BB * HH];         // partials (pre)
__device__ float g_splp[(size_t)8 * BB * NJ * 128];   // partials (spl1)
__device__ float g_hid[BB * HH];
__device__ float g_z1[BB * NJ * 128];
__device__ float g_xt[BB * DD];
__device__ float g_p6[BB * NJ * 6];

// ---------------- software grid barrier ---------------------------------------
__device__ unsigned g_barcnt = 0;
__device__ unsigned g_barsense = 0;

__device__ __forceinline__ void grid_bar() {
    __syncthreads();
    if (threadIdx.x == 0) {
        unsigned my = *(volatile unsigned*)&g_barsense;
        __threadfence();
        unsigned arrived = atomicAdd(&g_barcnt, 1u);
        if (arrived == NBLK - 1) {
            atomicExch(&g_barcnt, 0u);
            __threadfence();
            atomicExch(&g_barsense, my ^ 1u);
        } else {
            while (*(volatile unsigned*)&g_barsense == my) { }
            __threadfence();
        }
    }
    __syncthreads();
}

// ---------------- small utility kernels -------------------------------------

__global__ void copy_inseq_kernel(const float* __restrict__ poses, float* __restrict__ dst) {
    int idx = blockIdx.x * 256 + threadIdx.x;
    if (idx >= BB * TS * DD) return;
    int d = idx % DD;
    int t = (idx / DD) % TS;
    int b = idx / (TS * DD);
    dst[idx] = poses[((size_t)b * (TS + PREDN) + t) * DD + d];
}

__global__ void build_cos_kernel(float* __restrict__ cosm) {
    int idx = blockIdx.x * 256 + threadIdx.x;
    if (idx >= NF * TS) return;
    int f = idx / TS, t = idx % TS;
    cosm[idx] = (float)cos(2.0 * 3.14159265358979323846 * (double)(f * t) / (double)TS);
}

__global__ void freq_kernel(const float* __restrict__ inseq, const float* __restrict__ cosm,
                            float* __restrict__ freq) {
    int b = blockIdx.x, f = blockIdx.y, d = threadIdx.x;
    if (d >= DD) return;
    const float* xp = inseq + (size_t)b * TS * DD + d;
    const float* cp = cosm + f * TS;
    float s = 0.f;
    #pragma unroll 4
    for (int t = 0; t < TS; t++) s += cp[t] * xp[(size_t)t * DD];
    freq[((size_t)b * NF + f) * DD + d] = s;
}

// ---------------- weight splitter ---------------------------------------------
__global__ void split_w_kernel(const float* __restrict__ W, const float* __restrict__ bias,
                               __nv_bfloat16* __restrict__ hi, __nv_bfloat16* __restrict__ lo,
                               int N, int K, int KP) {
    size_t idx = (size_t)blockIdx.x * 256 + threadIdx.x;
    if (idx >= (size_t)N * KP) return;
    int n = (int)(idx / KP), k = (int)(idx % KP);
    float v = 0.f;
    if (k < K) v = W[(size_t)n * K + k];
    else if (k == K) v = bias[n];
    __nv_bfloat16 h = __float2bfloat16(v);
    hi[idx] = h;
    lo[idx] = __float2bfloat16(v - __bfloat162float(h));
}

// ---------------- error-compensated bf16 GEMM (batch / decode) ---------------
__global__ __launch_bounds__(256, 2) void gemm2_kernel(
    const float* __restrict__ A, const __nv_bfloat16* __restrict__ Whi,
    const __nv_bfloat16* __restrict__ Wlo, float* __restrict__ C,
    int M, int N, int K, int KP, int act)
{
    __shared__ __align__(16) __nv_bfloat16 AsH[128][40];
    __shared__ __align__(16) __nv_bfloat16 AsL[128][40];
    __shared__ __align__(16) __nv_bfloat16 WsH[128][40];
    __shared__ __align__(16) __nv_bfloat16 WsL[128][40];

    int tid = threadIdx.x;
    int warp = tid >> 5;
    int wm = warp >> 1, wn = warp & 1;
    int m0 = blockIdx.y * 128, n0 = blockIdx.x * 128;

    wmma::fragment<wmma::accumulator, 16, 16, 16, float> acc[2][4];
    #pragma unroll
    for (int i = 0; i < 2; i++)
        #pragma unroll
        for (int j = 0; j < 4; j++)
            wmma::fill_fragment(acc[i][j], 0.0f);

    int col  = tid & 31;
    int row0 = tid >> 5;

    int CH  = KP >> 5;
    int cpz = (CH + gridDim.z - 1) / gridDim.z;
    int c0  = blockIdx.z * cpz;
    int c1  = c0 + cpz; if (c1 > CH) c1 = CH;

    for (int c = c0; c < c1; c++) {
        int k0 = c << 5;
        if (k0 + 32 <= K) {
            #pragma unroll
            for (int i = 0; i < 16; i++) {
                int r = row0 + i * 8;
                float va = A[(size_t)(m0 + r) * K + k0 + col];
                __nv_bfloat16 ah = __float2bfloat16(va);
                AsH[r][col] = ah;
                AsL[r][col] = __float2bfloat16(va - __bfloat162float(ah));
            }
        } else {
            int gk = k0 + col;
            #pragma unroll
            for (int i = 0; i < 16; i++) {
                int r = row0 + i * 8;
                float va = (gk < K) ? A[(size_t)(m0 + r) * K + gk]
                                    : (gk == K ? 1.0f : 0.0f);
                __nv_bfloat16 ah = __float2bfloat16(va);
                AsH[r][col] = ah;
                AsL[r][col] = __float2bfloat16(va - __bfloat162float(ah));
            }
        }
        #pragma unroll
        for (int it = 0; it < 4; it++) {
            int slot = tid + it * 256;
            int rw = slot >> 3;
            int cg = (slot & 7) << 2;
            size_t goff = (size_t)(n0 + rw) * KP + k0 + cg;
            *(uint2*)&WsH[rw][cg] = *(const uint2*)(Whi + goff);
            *(uint2*)&WsL[rw][cg] = *(const uint2*)(Wlo + goff);
        }
        __syncthreads();
        #pragma unroll
        for (int kk = 0; kk < 32; kk += 16) {
            wmma::fragment<wmma::matrix_a, 16, 16, 16, __nv_bfloat16, wmma::row_major> faH[2], faL[2];
            #pragma unroll
            for (int i = 0; i < 2; i++) {
                wmma::load_matrix_sync(faH[i], &AsH[wm * 32 + i * 16][kk], 40);
                wmma::load_matrix_sync(faL[i], &AsL[wm * 32 + i * 16][kk], 40);
            }
            #pragma unroll
            for (int j = 0; j < 4; j++) {
                wmma::fragment<wmma::matrix_b, 16, 16, 16, __nv_bfloat16, wmma::col_major> fbH, fbL;
                wmma::load_matrix_sync(fbH, &WsH[wn * 64 + j * 16][kk], 40);
                wmma::load_matrix_sync(fbL, &WsL[wn * 64 + j * 16][kk], 40);
                #pragma unroll
                for (int i = 0; i < 2; i++) {
                    wmma::mma_sync(acc[i][j], faH[i], fbH, acc[i][j]);
                    wmma::mma_sync(acc[i][j], faH[i], fbL, acc[i][j]);
                    wmma::mma_sync(acc[i][j], faL[i], fbH, acc[i][j]);
                }
            }
        }
        __syncthreads();
    }

    float* Cz = C + (size_t)blockIdx.z * M * N;
    #pragma unroll
    for (int i = 0; i < 2; i++) {
        #pragma unroll
        for (int j = 0; j < 4; j++) {
            if (act == 1) {
                #pragma unroll
                for (int e = 0; e < acc[i][j].num_elements; e++)
                    acc[i][j].x[e] = fmaxf(acc[i][j].x[e], 0.0f);
            }
            wmma::store_matrix_sync(
                Cz + (size_t)(m0 + wm * 32 + i * 16) * N + (n0 + wn * 64 + j * 16),
                acc[i][j], N, wmma::mem_row_major);
        }
    }
}

// ---------------- persistent GRU recurrence (one launch per layer) -----------
// Per step: phase1 = gh partials (48 tiles x 3 k-slices), barrier,
//           phase2 = gate math h update (+optional seqout), barrier.
// h and ghp are cross-CTA within one launch -> __ldcg (bypass L1).
__global__ __launch_bounds__(256, 1) void gru_persist_kernel(
    const float* __restrict__ gi,          // (B, TS, GG), bih fused
    const __nv_bfloat16* __restrict__ Whi, // (GG, KP1024), bhh in col HH
    const __nv_bfloat16* __restrict__ Wlo,
    float* __restrict__ h,                 // (B, HH), pre-zeroed
    float* __restrict__ ghp,               // (3, B, GG) partials
    float* __restrict__ seqout,            // (B, TS, HH) or null
    int nsteps)
{
    __shared__ __align__(16) __nv_bfloat16 AsH[128][40];
    __shared__ __align__(16) __nv_bfloat16 AsL[128][40];
    __shared__ __align__(16) __nv_bfloat16 WsH[128][40];
    __shared__ __align__(16) __nv_bfloat16 WsL[128][40];

    int tid = threadIdx.x;
    int warp = tid >> 5;
    int wm = warp >> 1, wn = warp & 1;
    int tile  = blockIdx.x % 48;
    int slice = blockIdx.x / 48;           // 0..2
    int m0 = (tile / 24) * 128;
    int n0 = (tile % 24) * 128;
    int col = tid & 31, row0 = tid >> 5;

    for (int t = 0; t < nsteps; t++) {
        // ---- phase 1: partial gh = h @ Whh^T over k-slice ----
        wmma::fragment<wmma::accumulator, 16, 16, 16, float> acc[2][4];
        #pragma unroll
        for (int i = 0; i < 2; i++)
            #pragma unroll
            for (int j = 0; j < 4; j++)
                wmma::fill_fragment(acc[i][j], 0.0f);

        for (int c = slice * 11; c < slice * 11 + 11; c++) {
            int k0 = c << 5;
            if (k0 + 32 <= HH) {
                #pragma unroll
                for (int i = 0; i < 16; i++) {
                    int r = row0 + i * 8;
                    float va = __ldcg(&h[(size_t)(m0 + r) * HH + k0 + col]);
                    __nv_bfloat16 ah = __float2bfloat16(va);
                    AsH[r][col] = ah;
                    AsL[r][col] = __float2bfloat16(va - __bfloat162float(ah));
                }
            } else {
                int gk = k0 + col;
                #pragma unroll
                for (int i = 0; i < 16; i++) {
                    int r = row0 + i * 8;
                    float va = (gk < HH) ? __ldcg(&h[(size_t)(m0 + r) * HH + gk])
                                         : (gk == HH ? 1.0f : 0.0f);
                    __nv_bfloat16 ah = __float2bfloat16(va);
                    AsH[r][col] = ah;
                    AsL[r][col] = __float2bfloat16(va - __bfloat162float(ah));
                }
            }
            #pragma unroll
            for (int it = 0; it < 4; it++) {
                int slot = tid + it * 256;
                int rw = slot >> 3;
                int cg = (slot & 7) << 2;
                size_t goff = (size_t)(n0 + rw) * KP1024 + k0 + cg;
                *(uint2*)&WsH[rw][cg] = *(const uint2*)(Whi + goff);
                *(uint2*)&WsL[rw][cg] = *(const uint2*)(Wlo + goff);
            }
            __syncthreads();
            #pragma unroll
            for (int kk = 0; kk < 32; kk += 16) {
                wmma::fragment<wmma::matrix_a, 16, 16, 16, __nv_bfloat16, wmma::row_major> faH[2], faL[2];
                #pragma unroll
                for (int i = 0; i < 2; i++) {
                    wmma::load_matrix_sync(faH[i], &AsH[wm * 32 + i * 16][kk], 40);
                    wmma::load_matrix_sync(faL[i], &AsL[wm * 32 + i * 16][kk], 40);
                }
                #pragma unroll
                for (int j = 0; j < 4; j++) {
                    wmma::fragment<wmma::matrix_b, 16, 16, 16, __nv_bfloat16, wmma::col_major> fbH, fbL;
                    wmma::load_matrix_sync(fbH, &WsH[wn * 64 + j * 16][kk], 40);
                    wmma::load_matrix_sync(fbL, &WsL[wn * 64 + j * 16][kk], 40);
                    #pragma unroll
                    for (int i = 0; i < 2; i++) {
                        wmma::mma_sync(acc[i][j], faH[i], fbH, acc[i][j]);
                        wmma::mma_sync(acc[i][j], faH[i], fbL, acc[i][j]);
                        wmma::mma_sync(acc[i][j], faL[i], fbH, acc[i][j]);
                    }
                }
            }
            __syncthreads();
        }

        float* Cz = ghp + (size_t)slice * (BB * GG);
        #pragma unroll
        for (int i = 0; i < 2; i++)
            #pragma unroll
            for (int j = 0; j < 4; j++)
                wmma::store_matrix_sync(
                    Cz + (size_t)(m0 + wm * 32 + i * 16) * GG + (n0 + wn * 64 + j * 16),
                    acc[i][j], GG, wmma::mem_row_major);

        __threadfence();
        grid_bar();

        // ---- phase 2: gate math ----
        for (int idx = blockIdx.x * 256 + tid; idx < BB * HH; idx += NBLK * 256) {
            int b = idx >> 10, j = idx & 1023;
            const float* gib = gi + ((size_t)b * TS + t) * GG;
            float ir = gib[j], iz = gib[HH + j], inn = gib[2 * HH + j];
            float hr = 0.f, hz = 0.f, hn = 0.f;
            #pragma unroll
            for (int s = 0; s < 3; s++) {
                const float* g = ghp + (size_t)s * (BB * GG) + (size_t)b * GG;
                hr += __ldcg(&g[j]);
                hz += __ldcg(&g[HH + j]);
                hn += __ldcg(&g[2 * HH + j]);
            }
            float r = 1.f / (1.f + expf(-(ir + hr)));
            float z = 1.f / (1.f + expf(-(iz + hz)));
            float n = tanhf(inn + r * hn);
            float hp = __ldcg(&h[idx]);
            float hnew = (1.f - z) * n + z * hp;
            h[idx] = hnew;
            if (seqout) seqout[((size_t)b * TS + t) * HH + j] = hnew;
        }
        __threadfence();
        grid_bar();
    }
}

// ---------------- attention ---------------------------------------------------
__global__ __launch_bounds__(256) void attention_kernel(const float* __restrict__ qkv,
                                                        float* __restrict__ o) {
    extern __shared__ float sm[];
    float* kv = sm;
    float* sc = sm + NF * DHD;
    int b = blockIdx.x >> 2;
    int h = blockIdx.x & 3;
    int tid = threadIdx.x;
    int lane = tid & 31, w = tid >> 5;
    const float* base = qkv + (size_t)b * NF * GG + h * DHD;

    for (int idx = tid; idx < NF * DHD; idx += 256) {
        int t = idx >> 8, d = idx & 255;
        kv[idx] = base[(size_t)t * GG + HH + d];
    }
    __syncthreads();
    for (int i = w; i < NF; i += 8) {
        float q[8];
        const float* qp = base + (size_t)i * GG;
        #pragma unroll
        for (int c = 0; c < 8; c++) q[c] = qp[lane + 32 * c];
        for (int j = 0; j < NF; j++) {
            const float* kp = kv + j * DHD;
            float s = 0.f;
            #pragma unroll
            for (int c = 0; c < 8; c++) s += q[c] * kp[lane + 32 * c];
            #pragma unroll
            for (int off = 16; off; off >>= 1) s += __shfl_xor_sync(0xffffffffu, s, off);
            if (lane == 0) sc[i * 64 + j] = s * 0.0625f;
        }
    }
    __syncthreads();
    for (int i = w; i < NF; i += 8) {
        float v0 = (lane < NF) ? sc[i * 64 + lane] : -1e30f;
        float v1 = (lane + 32 < NF) ? sc[i * 64 + lane + 32] : -1e30f;
        float m = fmaxf(v0, v1);
        #pragma unroll
        for (int off = 16; off; off >>= 1) m = fmaxf(m, __shfl_xor_sync(0xffffffffu, m, off));
        float e0 = (lane < NF) ? expf(v0 - m) : 0.f;
        float e1 = (lane + 32 < NF) ? expf(v1 - m) : 0.f;
        float ss = e0 + e1;
        #pragma unroll
        for (int off = 16; off; off >>= 1) ss += __shfl_xor_sync(0xffffffffu, ss, off);
        float inv = 1.f / ss;
        if (lane < NF) sc[i * 64 + lane] = e0 * inv;
        if (lane + 32 < NF) sc[i * 64 + lane + 32] = e1 * inv;
    }
    __syncthreads();
    for (int idx = tid; idx < NF * DHD; idx += 256) {
        int t = idx >> 8, d = idx & 255;
        kv[idx] = base[(size_t)t * GG + 2 * HH + d];
    }
    __syncthreads();
    float acc[NF];
    #pragma unroll
    for (int i = 0; i < NF; i++) acc[i] = 0.f;
    int d = tid;
    for (int j = 0; j < NF; j++) {
        float vv = kv[j * DHD + d];
        #pragma unroll
        for (int i = 0; i < NF; i++) acc[i] += sc[i * 64 + j] * vv;
    }
    float* ob = o + (size_t)b * NF * HH + h * DHD + d;
    #pragma unroll
    for (int i = 0; i < NF; i++) ob[(size_t)i * HH] = acc[i];
}

__global__ void mean61_kernel(const float* __restrict__ o, float* __restrict__ obar) {
    int idx = blockIdx.x * 256 + threadIdx.x;
    if (idx >= BB * HH) return;
    int b = idx >> 10, c = idx & 1023;
    const float* p = o + (size_t)b * NF * HH + c;
    float s = 0.f;
    for (int t = 0; t < NF; t++) s += p[(size_t)t * HH];
    obar[idx] = s * (1.f / (float)NF);
}

// ---------------- GRU gate math (decode; split-K aware) -----------------------
__global__ void gru_gate2(const float* __restrict__ gi, size_t gi_rs, int gi_sk, size_t gi_ss,
                          const float* __restrict__ ghp, int gh_sk,
                          float* __restrict__ h,
                          float* __restrict__ seqout, size_t seq_rs) {
    int idx = blockIdx.x * 256 + threadIdx.x;
    if (idx >= BB * HH) return;
    int b = idx >> 10, j = idx & 1023;
    float ir = 0.f, iz = 0.f, in = 0.f;
    for (int s = 0; s < gi_sk; s++) {
        const float* g = gi + (size_t)s * gi_ss + (size_t)b * gi_rs;
        ir += g[j]; iz += g[HH + j]; in += g[2 * HH + j];
    }
    float hr = 0.f, hz = 0.f, hn = 0.f;
    for (int s = 0; s < gh_sk; s++) {
        const float* g = ghp + (size_t)s * (BB * GG) + (size_t)b * GG;
        hr += g[j]; hz += g[HH + j]; hn += g[2 * HH + j];
    }
    float r = 1.f / (1.f + expf(-(ir + hr)));
    float z = 1.f / (1.f + expf(-(iz + hz)));
    float n = tanhf(in + r * hn);
    float hp = h[idx];
    float hnew = (1.f - z) * n + z * hp;
    h[idx] = hnew;
    if (seqout) seqout[(size_t)b * seq_rs + j] = hnew;
}

__global__ void reduce_act_kernel(const float* __restrict__ part, int sk, int mn,
                                  const float* __restrict__ addend,
                                  float* __restrict__ out, int act) {
    int idx = blockIdx.x * 256 + threadIdx.x;
    if (idx >= mn) return;
    float s = 0.f;
    for (int i = 0; i < sk; i++) s += part[(size_t)i * mn + idx];
    if (act) s = fmaxf(s, 0.f);
    if (addend) s += addend[idx];
    out[idx] = s;
}

// ---------------- decode init --------------------------------------------------
__global__ void init_decode(const float* __restrict__ inseq,
                            float* __restrict__ xt, float* __restrict__ p6) {
    int idx = blockIdx.x * 256 + threadIdx.x;
    if (idx >= BB * DD) return;
    int b = idx / DD, d = idx % DD;
    const float* last = inseq + ((size_t)b * TS + (TS - 1)) * DD;
    xt[idx] = last[d];
    if (d < NJ * 6) {
        int j = d / 6, o = d % 6;
        int src = (o < 3) ? (j * 9 + o * 3) : (j * 9 + (o - 3) * 3 + 1);
        p6[(size_t)b * 90 + d] = last[src];
    }
}

// ---------------- spl head layer2 + rot6d --------------------------------------
__global__ __launch_bounds__(192) void spl2_rot(const float* __restrict__ z1,
                                                const float* __restrict__ w2,
                                                const float* __restrict__ b2,
                                                float* __restrict__ p6,
                                                float* __restrict__ xt,
                                                float* __restrict__ out, int step) {
    int bj = blockIdx.x;
    int b = bj / NJ, j = bj % NJ;
    int w = threadIdx.x >> 5, lane = threadIdx.x & 31;
    __shared__ float v6[6];
    const float* zz = z1 + (size_t)b * (NJ * 128) + j * 128;
    const float* ww = w2 + ((size_t)j * 6 + w) * 128;
    float s = 0.f;
    #pragma unroll
    for (int c = 0; c < 4; c++) s += zz[lane + 32 * c] * ww[lane + 32 * c];
    #pragma unroll
    for (int off = 16; off; off >>= 1) s += __shfl_xor_sync(0xffffffffu, s, off);
    if (lane == 0)
        v6[w] = p6[(size_t)b * 90 + j * 6 + w] + s + b2[j * 6 + w];
    __syncthreads();
    if (threadIdx.x < 6) {
        float v = v6[threadIdx.x];
        p6[(size_t)b * 90 + j * 6 + threadIdx.x] = v;
        out[((size_t)b * PREDN + step) * 90 + j * 6 + threadIdx.x] = v;
    }
    if (threadIdx.x == 0) {
        float a1x = v6[0], a2x = v6[1], a1y = v6[2], a2y = v6[3], a1z = v6[4], a2z = v6[5];
        float n1 = fmaxf(sqrtf(a1x*a1x + a1y*a1y + a1z*a1z), 1e-12f);
        float b1x = a1x / n1, b1y = a1y / n1, b1z = a1z / n1;
        float dot = b1x*a2x + b1y*a2y + b1z*a2z;
        float ox = a2x - dot*b1x, oy = a2y - dot*b1y, oz = a2z - dot*b1z;
        float n2 = fmaxf(sqrtf(ox*ox + oy*oy + oz*oz), 1e-12f);
        float b2x = ox / n2, b2y = oy / n2, b2z = oz / n2;
        float b3x = b1y*b2z - b1z*b2y;
        float b3y = b1z*b2x - b1x*b2z;
        float b3z = b1x*b2y - b1y*b2x;
        float* xo = xt + (size_t)b * DD + j * 9;
        xo[0] = b1x; xo[1] = b2x; xo[2] = b3x;
        xo[3] = b1y; xo[4] = b2y; xo[5] = b3y;
        xo[6] = b1z; xo[7] = b2z; xo[8] = b3z;
    }
}

// ---------------- host orchestration -------------------------------------------

static inline void gemm2(const float* A, const __nv_bfloat16* whi, const __nv_bfloat16* wlo,
                         float* C, int M, int N, int K, int KP, int act, int sk) {
    dim3 g(N / 128, M / 128, sk);
    gemm2_kernel<<<g, 256>>>(A, whi, wlo, C, M, N, K, KP, act);
}

static inline void splitw(const float* W, const float* bias,
                          __nv_bfloat16* hi, __nv_bfloat16* lo, int N, int K, int KP) {
    size_t n = (size_t)N * KP;
    split_w_kernel<<<(int)((n + 255) / 256), 256>>>(W, bias, hi, lo, N, K, KP);
}

extern "C" void kernel_launch(void* const* d_in, const int* in_sizes, int n_in,
                              void* d_out, int out_size) {
    const float* poses      = (const float*)d_in[0];
    const float* freq_w     = (const float*)d_in[1];
    const float* freq_b     = (const float*)d_in[2];
    const float* attn_in_w  = (const float*)d_in[3];
    const float* attn_in_b  = (const float*)d_in[4];
    const float* attn_out_w = (const float*)d_in[5];
    const float* attn_out_b = (const float*)d_in[6];
    const float* gru_wih0   = (const float*)d_in[7];
    const float* gru_whh0   = (const float*)d_in[8];
    const float* gru_bih0   = (const float*)d_in[9];
    const float* gru_bhh0   = (const float*)d_in[10];
    const float* gru_wih1   = (const float*)d_in[11];
    const float* gru_whh1   = (const float*)d_in[12];
    const float* gru_bih1   = (const float*)d_in[13];
    const float* gru_bhh1   = (const float*)d_in[14];
    const float* pre_w      = (const float*)d_in[15];
    const float* pre_b      = (const float*)d_in[16];
    const float* spl_w1     = (const float*)d_in[17];
    const float* spl_b1     = (const float*)d_in[18];
    const float* spl_w2     = (const float*)d_in[19];
    const float* spl_b2     = (const float*)d_in[20];
    float* out = (float*)d_out;

    float *pBig, *pSeq, *pIn, *pFrq, *pCos, *pObar, *pMctx, *pH0, *pH1,
          *pGhp, *pGxp, *pPrep, *pSplp, *pHid, *pZ1, *pXt, *pP6;
    __nv_bfloat16 *pWhi, *pWlo;
    cudaGetSymbolAddress((void**)&pBig, g_big);
    cudaGetSymbolAddress((void**)&pSeq, g_seq);
    cudaGetSymbolAddress((void**)&pIn,  g_in);
    cudaGetSymbolAddress((void**)&pFrq, g_frq);
    cudaGetSymbolAddress((void**)&pCos, g_cosm);
    cudaGetSymbolAddress((void**)&pObar, g_obar);
    cudaGetSymbolAddress((void**)&pMctx, g_mctx);
    cudaGetSymbolAddress((void**)&pH0, g_h0);
    cudaGetSymbolAddress((void**)&pH1, g_h1);
    cudaGetSymbolAddress((void**)&pGhp, g_ghp);
    cudaGetSymbolAddress((void**)&pGxp, g_gxp);
    cudaGetSymbolAddress((void**)&pPrep, g_prep);
    cudaGetSymbolAddress((void**)&pSplp, g_splp);
    cudaGetSymbolAddress((void**)&pHid, g_hid);
    cudaGetSymbolAddress((void**)&pZ1, g_z1);
    cudaGetSymbolAddress((void**)&pXt, g_xt);
    cudaGetSymbolAddress((void**)&pP6, g_p6);
    cudaGetSymbolAddress((void**)&pWhi, g_whi);
    cudaGetSymbolAddress((void**)&pWlo, g_wlo);

    float* qkv   = pBig;
    float* attno = pBig + (size_t)BB * NF * GG;
    float* gi    = pBig;
    float* feat  = pSeq;
    float* seq0  = pSeq;

    const int BF = BB * NF;   // 15616
    const int BT = BB * TS;   // 30720

    // ---- one-time weight splits ----
    splitw(attn_in_w, attn_in_b, pWhi + OFF_ATTNIN,  pWlo + OFF_ATTNIN,  GG, HH, KP1024);
    splitw(gru_wih0,  gru_bih0,  pWhi + OFF_WIH0,    pWlo + OFF_WIH0,    GG, DD, KP135);
    splitw(gru_whh0,  gru_bhh0,  pWhi + OFF_WHH0,    pWlo + OFF_WHH0,    GG, HH, KP1024);
    splitw(gru_wih1,  gru_bih1,  pWhi + OFF_WIH1,    pWlo + OFF_WIH1,    GG, HH, KP1024);
    splitw(gru_whh1,  gru_bhh1,  pWhi + OFF_WHH1,    pWlo + OFF_WHH1,    GG, HH, KP1024);
    splitw(freq_w,    freq_b,    pWhi + OFF_FREQ,    pWlo + OFF_FREQ,    HH, DD, KP135);
    splitw(attn_out_w,attn_out_b,pWhi + OFF_ATTNOUT, pWlo + OFF_ATTNOUT, HH, HH, KP1024);
    splitw(pre_w,     pre_b,     pWhi + OFF_PRE,     pWlo + OFF_PRE,     HH, HH, KP1024);
    splitw(spl_w1,    spl_b1,    pWhi + OFF_SPL1,    pWlo + OFF_SPL1,    NJ*128, HH, KP1024);

    // ---- frequency attention branch ----
    copy_inseq_kernel<<<(BB*TS*DD + 255) / 256, 256>>>(poses, pIn);
    build_cos_kernel<<<(NF*TS + 255) / 256, 256>>>(pCos);
    freq_kernel<<<dim3(BB, NF), 160>>>(pIn, pCos, pFrq);
    gemm2(pFrq, pWhi + OFF_FREQ, pWlo + OFF_FREQ, feat, BF, HH, DD, KP135, 0, 1);
    gemm2(feat, pWhi + OFF_ATTNIN, pWlo + OFF_ATTNIN, qkv, BF, GG, HH, KP1024, 0, 1);

    int smem_attn = (NF * DHD + NF * 64) * (int)sizeof(float);
    cudaFuncSetAttribute(attention_kernel, cudaFuncAttributeMaxDynamicSharedMemorySize, smem_attn);
    attention_kernel<<<BB * NHEAD, 256, smem_attn>>>(qkv, attno);
    mean61_kernel<<<(BB*HH + 255) / 256, 256>>>(attno, pObar);
    gemm2(pObar, pWhi + OFF_ATTNOUT, pWlo + OFF_ATTNOUT, pMctx, BB, HH, HH, KP1024, 0, 1);

    // ---- GRU layer 0 (persistent recurrence) ----
    gemm2(pIn, pWhi + OFF_WIH0, pWlo + OFF_WIH0, gi, BT, GG, DD, KP135, 0, 1);
    cudaMemsetAsync(pH0, 0, (size_t)BB * HH * sizeof(float));
    gru_persist_kernel<<<NBLK, 256>>>(gi, pWhi + OFF_WHH0, pWlo + OFF_WHH0,
                                      pH0, pGhp, seq0, TS);

    // ---- GRU layer 1 (persistent recurrence) ----
    gemm2(seq0, pWhi + OFF_WIH1, pWlo + OFF_WIH1, gi, BT, GG, HH, KP1024, 0, 1);
    cudaMemsetAsync(pH1, 0, (size_t)BB * HH * sizeof(float));
    gru_persist_kernel<<<NBLK, 256>>>(gi, pWhi + OFF_WHH1, pWlo + OFF_WHH1,
                                      pH1, pGhp, nullptr, TS);

    // ---- autoregressive decode ----
    init_decode<<<(BB*DD + 255) / 256, 256>>>(pIn, pXt, pP6);
    for (int s = 0; s < PREDN; s++) {
        gemm2(pXt, pWhi + OFF_WIH0, pWlo + OFF_WIH0, pGxp, BB, GG, DD, KP135, 0, 2);
        gemm2(pH0, pWhi + OFF_WHH0, pWlo + OFF_WHH0, pGhp, BB, GG, HH, KP1024, 0, 4);
        gru_gate2<<<(BB*HH)/256, 256>>>(pGxp, GG, 2, (size_t)BB * GG,
                                        pGhp, 4, pH0, nullptr, 0);

        gemm2(pH0, pWhi + OFF_WIH1, pWlo + OFF_WIH1, pGxp, BB, GG, HH, KP1024, 0, 4);
        gemm2(pH1, pWhi + OFF_WHH1, pWlo + OFF_WHH1, pGhp, BB, GG, HH, KP1024, 0, 4);
        gru_gate2<<<(BB*HH)/256, 256>>>(pGxp, GG, 4, (size_t)BB * GG,
                                        pGhp, 4, pH1, nullptr, 0);

        gemm2(pH1, pWhi + OFF_PRE, pWlo + OFF_PRE, pPrep, BB, HH, HH, KP1024, 0, 8);
        reduce_act_kernel<<<(BB*HH + 255)/256, 256>>>(pPrep, 8, BB*HH, pMctx, pHid, 1);

        gemm2(pHid, pWhi + OFF_SPL1, pWlo + OFF_SPL1, pSplp, BB, NJ*128, HH, KP1024, 0, 8);
        reduce_act_kernel<<<(BB*NJ*128 + 255)/256, 256>>>(pSplp, 8, BB*NJ*128, nullptr, pZ1, 1);

        spl2_rot<<<BB * NJ, 192>>>(pZ1, spl_w2, spl_b2, pP6, pXt, out, s);
    }
}

// round 6
// speedup vs baseline: 2.8734x; 1.1941x over previous
#include <cuda_runtime.h>
#include <cuda_bf16.h>
#include <mma.h>
#include <math.h>

using namespace nvcuda;

#define BB    256
#define TS    120
#define PREDN 24
#define NJ    15
#define HH    1024
#define DD    135
#define NF    61        // rfft length = TS/2+1
#define GG    3072      // 3*H
#define NHEAD 4
#define DHD   256       // H / NHEAD

// padded K (bias column appended, rounded to 32)
#define KP1024 1056
#define KP135  160

#define NBLK  144       // persistent grid size (<= 148 SMs -> co-resident)

typedef __nv_bfloat16 bf16;

// ---------------- weight split pools (bf16 hi/lo) ----------------------------
#define OFF_ATTNIN  0ull
#define OFF_WIH0    3244032ull
#define OFF_WHH0    3735552ull
#define OFF_WIH1    6979584ull
#define OFF_WHH1    10223616ull
#define OFF_FREQ    13467648ull
#define OFF_ATTNOUT 13631488ull
#define OFF_PRE     14712832ull
#define OFF_SPL1    15794176ull
#define WPOOL_TOTAL 17821696ull

__device__ bf16 g_whi[WPOOL_TOTAL];
__device__ bf16 g_wlo[WPOOL_TOTAL];

// ---------------- activation split pool (bf16 hi/lo) -------------------------
#define OFFA_IN    0ull          // (BT, 160)
#define OFFA_FRQ   4915200ull    // (BF, 160)
#define OFFA_FEAT  7413760ull    // (BF, 1056)
#define OFFA_SEQ   23904256ull   // (BT, 1056)
#define OFFA_OBAR  56344576ull   // (256, 1056)
#define OFFA_H0    56614912ull   // (256, 1056)
#define OFFA_H1    56885248ull   // (256, 1056)
#define OFFA_HID   57155584ull   // (256, 1056)
#define OFFA_XT    57425920ull   // (256, 160)
#define APOOL_TOTAL 57466880ull

__device__ bf16 g_ahi[APOOL_TOTAL];
__device__ bf16 g_alo[APOOL_TOTAL];

// ---------------- scratch buffers ---------------------------------------------
__device__ float g_big[(size_t)BB * TS * GG];         // gi / qkv / attn-out (aliased)
__device__ float g_seq[(size_t)BB * TS * HH];         // feat fp32 (aliased region)
__device__ float g_in [(size_t)BB * TS * DD];
__device__ float g_frq[(size_t)BB * NF * DD];
__device__ float g_cosm[NF * TS];
__device__ float g_obar[BB * HH];
__device__ float g_mctx[BB * HH];
__device__ float g_h0[BB * HH];
__device__ float g_h1[BB * HH];
__device__ float g_ghp[(size_t)4 * BB * GG];          // partials (gh)
__device__ float g_gxp[(size_t)4 * BB * GG];          // partials (gx)
__device__ float g_prep[(size_t)8 * BB * HH];         // partials (pre)
__device__ float g_splp[(size_t)8 * BB * NJ * 128];   // partials (spl1)
__device__ float g_z1[BB * NJ * 128];
__device__ float g_p6[BB * NJ * 6];

// ---------------- software grid barrier ---------------------------------------
__device__ unsigned g_barcnt = 0;
__device__ unsigned g_barsense = 0;

__device__ __forceinline__ void grid_bar() {
    __syncthreads();
    if (threadIdx.x == 0) {
        unsigned my = *(volatile unsigned*)&g_barsense;
        __threadfence();
        unsigned arrived = atomicAdd(&g_barcnt, 1u);
        if (arrived == NBLK - 1) {
            atomicExch(&g_barcnt, 0u);
            __threadfence();
            atomicExch(&g_barsense, my ^ 1u);
        } else {
            while (*(volatile unsigned*)&g_barsense == my) { }
            __threadfence();
        }
    }
    __syncthreads();
}

// ---------------- small utility kernels -------------------------------------

__global__ void copy_inseq_kernel(const float* __restrict__ poses, float* __restrict__ dst) {
    int idx = blockIdx.x * 256 + threadIdx.x;
    if (idx >= BB * TS * DD) return;
    int d = idx % DD;
    int t = (idx / DD) % TS;
    int b = idx / (TS * DD);
    dst[idx] = poses[((size_t)b * (TS + PREDN) + t) * DD + d];
}

__global__ void build_cos_kernel(float* __restrict__ cosm) {
    int idx = blockIdx.x * 256 + threadIdx.x;
    if (idx >= NF * TS) return;
    int f = idx / TS, t = idx % TS;
    cosm[idx] = (float)cos(2.0 * 3.14159265358979323846 * (double)(f * t) / (double)TS);
}

__global__ void freq_kernel(const float* __restrict__ inseq, const float* __restrict__ cosm,
                            float* __restrict__ freq) {
    int b = blockIdx.x, f = blockIdx.y, d = threadIdx.x;
    if (d >= DD) return;
    const float* xp = inseq + (size_t)b * TS * DD + d;
    const float* cp = cosm + f * TS;
    float s = 0.f;
    #pragma unroll 4
    for (int t = 0; t < TS; t++) s += cp[t] * xp[(size_t)t * DD];
    freq[((size_t)b * NF + f) * DD + d] = s;
}

// ---------------- weight/activation splitters ---------------------------------
__global__ void split_w_kernel(const float* __restrict__ W, const float* __restrict__ bias,
                               bf16* __restrict__ hi, bf16* __restrict__ lo,
                               int N, int K, int KP) {
    size_t idx = (size_t)blockIdx.x * 256 + threadIdx.x;
    if (idx >= (size_t)N * KP) return;
    int k = (int)(idx % KP);
    int n = (int)(idx / KP);
    float v = 0.f;
    if (k < K) v = W[(size_t)n * K + k];
    else if (k == K) v = bias[n];
    bf16 h = __float2bfloat16(v);
    hi[idx] = h;
    lo[idx] = __float2bfloat16(v - __bfloat162float(h));
}

// A (M,K) fp32 -> (M,KP) bf16 hi/lo with ones-column at k==K
__global__ void split_a_kernel(const float* __restrict__ A,
                               bf16* __restrict__ hi, bf16* __restrict__ lo,
                               int M, int K, int KP) {
    size_t idx = (size_t)blockIdx.x * 256 + threadIdx.x;
    if (idx >= (size_t)M * KP) return;
    int k = (int)(idx % KP);
    int m = (int)(idx / KP);
    float v = 0.f;
    if (k < K) v = A[(size_t)m * K + k];
    else if (k == K) v = 1.0f;
    bf16 h = __float2bfloat16(v);
    hi[idx] = h;
    lo[idx] = __float2bfloat16(v - __bfloat162float(h));
}

// zero data cols, set ones-column at k==K (for buffers whose data cols are
// written later by producer kernels)
__global__ void zero_split_kernel(bf16* __restrict__ hi, bf16* __restrict__ lo,
                                  int M, int K, int KP) {
    size_t idx = (size_t)blockIdx.x * 256 + threadIdx.x;
    if (idx >= (size_t)M * KP) return;
    int k = (int)(idx % KP);
    float v = (k == K) ? 1.0f : 0.0f;
    hi[idx] = __float2bfloat16(v);
    lo[idx] = __float2bfloat16(0.0f);
}

// ---------------- fully pre-split bf16 GEMM ------------------------------------
// C = A(M,KP) * W(N,KP)^T, both pre-split bf16 hi/lo, fp32 out.
// 3-term compensated product. Split-K via gridDim.z (slice z writes C+z*M*N).
__global__ __launch_bounds__(256, 2) void gemm3_kernel(
    const bf16* __restrict__ Ahi, const bf16* __restrict__ Alo,
    const bf16* __restrict__ Whi, const bf16* __restrict__ Wlo,
    float* __restrict__ C, int M, int N, int KP)
{
    __shared__ __align__(16) bf16 AsH[128][40];
    __shared__ __align__(16) bf16 AsL[128][40];
    __shared__ __align__(16) bf16 WsH[128][40];
    __shared__ __align__(16) bf16 WsL[128][40];

    int tid = threadIdx.x;
    int warp = tid >> 5;
    int wm = warp >> 1, wn = warp & 1;
    int m0 = blockIdx.y * 128, n0 = blockIdx.x * 128;

    wmma::fragment<wmma::accumulator, 16, 16, 16, float> acc[2][4];
    #pragma unroll
    for (int i = 0; i < 2; i++)
        #pragma unroll
        for (int j = 0; j < 4; j++)
            wmma::fill_fragment(acc[i][j], 0.0f);

    int CH  = KP >> 5;
    int cpz = (CH + gridDim.z - 1) / gridDim.z;
    int c0  = blockIdx.z * cpz;
    int c1  = c0 + cpz; if (c1 > CH) c1 = CH;

    for (int c = c0; c < c1; c++) {
        int k0 = c << 5;
        #pragma unroll
        for (int it = 0; it < 4; it++) {
            int slot = tid + it * 256;
            int rw = slot >> 3;
            int cg = (slot & 7) << 2;
            size_t aoff = (size_t)(m0 + rw) * KP + k0 + cg;
            *(uint2*)&AsH[rw][cg] = *(const uint2*)(Ahi + aoff);
            *(uint2*)&AsL[rw][cg] = *(const uint2*)(Alo + aoff);
            size_t woff = (size_t)(n0 + rw) * KP + k0 + cg;
            *(uint2*)&WsH[rw][cg] = *(const uint2*)(Whi + woff);
            *(uint2*)&WsL[rw][cg] = *(const uint2*)(Wlo + woff);
        }
        __syncthreads();
        #pragma unroll
        for (int kk = 0; kk < 32; kk += 16) {
            wmma::fragment<wmma::matrix_a, 16, 16, 16, bf16, wmma::row_major> faH[2], faL[2];
            #pragma unroll
            for (int i = 0; i < 2; i++) {
                wmma::load_matrix_sync(faH[i], &AsH[wm * 32 + i * 16][kk], 40);
                wmma::load_matrix_sync(faL[i], &AsL[wm * 32 + i * 16][kk], 40);
            }
            #pragma unroll
            for (int j = 0; j < 4; j++) {
                wmma::fragment<wmma::matrix_b, 16, 16, 16, bf16, wmma::col_major> fbH, fbL;
                wmma::load_matrix_sync(fbH, &WsH[wn * 64 + j * 16][kk], 40);
                wmma::load_matrix_sync(fbL, &WsL[wn * 64 + j * 16][kk], 40);
                #pragma unroll
                for (int i = 0; i < 2; i++) {
                    wmma::mma_sync(acc[i][j], faH[i], fbH, acc[i][j]);
                    wmma::mma_sync(acc[i][j], faH[i], fbL, acc[i][j]);
                    wmma::mma_sync(acc[i][j], faL[i], fbH, acc[i][j]);
                }
            }
        }
        __syncthreads();
    }

    float* Cz = C + (size_t)blockIdx.z * M * N;
    #pragma unroll
    for (int i = 0; i < 2; i++)
        #pragma unroll
        for (int j = 0; j < 4; j++)
            wmma::store_matrix_sync(
                Cz + (size_t)(m0 + wm * 32 + i * 16) * N + (n0 + wn * 64 + j * 16),
                acc[i][j], N, wmma::mem_row_major);
}

// ---------------- persistent GRU recurrence (one launch per layer) -----------
// h kept in BOTH fp32 (for gate recursion) and pre-split bf16 (GEMM operand).
__global__ __launch_bounds__(256, 1) void gru_persist_kernel(
    const float* __restrict__ gi,          // (B, TS, GG), bih fused
    const bf16* __restrict__ Whi,          // (GG, KP1024), bhh in col HH
    const bf16* __restrict__ Wlo,
    float* __restrict__ h,                 // (B, HH) fp32, pre-zeroed
    bf16* __restrict__ hhi,                // (B, KP1024), pre-inited (zero+ones col)
    bf16* __restrict__ hlo,
    float* __restrict__ ghp,               // (3, B, GG) partials
    bf16* __restrict__ seqhi,              // (B, TS, KP1024) or null
    bf16* __restrict__ seqlo,
    int nsteps)
{
    __shared__ __align__(16) bf16 AsH[128][40];
    __shared__ __align__(16) bf16 AsL[128][40];
    __shared__ __align__(16) bf16 WsH[128][40];
    __shared__ __align__(16) bf16 WsL[128][40];

    int tid = threadIdx.x;
    int warp = tid >> 5;
    int wm = warp >> 1, wn = warp & 1;
    int tile  = blockIdx.x % 48;
    int slice = blockIdx.x / 48;           // 0..2
    int m0 = (tile / 24) * 128;
    int n0 = (tile % 24) * 128;

    for (int t = 0; t < nsteps; t++) {
        // ---- phase 1: partial gh = h @ Whh^T over this k-slice ----
        wmma::fragment<wmma::accumulator, 16, 16, 16, float> acc[2][4];
        #pragma unroll
        for (int i = 0; i < 2; i++)
            #pragma unroll
            for (int j = 0; j < 4; j++)
                wmma::fill_fragment(acc[i][j], 0.0f);

        for (int c = slice * 11; c < slice * 11 + 11; c++) {
            int k0 = c << 5;
            #pragma unroll
            for (int it = 0; it < 4; it++) {
                int slot = tid + it * 256;
                int rw = slot >> 3;
                int cg = (slot & 7) << 2;
                size_t aoff = (size_t)(m0 + rw) * KP1024 + k0 + cg;
                *(uint2*)&AsH[rw][cg] = *(const uint2*)(hhi + aoff);
                *(uint2*)&AsL[rw][cg] = *(const uint2*)(hlo + aoff);
                size_t woff = (size_t)(n0 + rw) * KP1024 + k0 + cg;
                *(uint2*)&WsH[rw][cg] = *(const uint2*)(Whi + woff);
                *(uint2*)&WsL[rw][cg] = *(const uint2*)(Wlo + woff);
            }
            __syncthreads();
            #pragma unroll
            for (int kk = 0; kk < 32; kk += 16) {
                wmma::fragment<wmma::matrix_a, 16, 16, 16, bf16, wmma::row_major> faH[2], faL[2];
                #pragma unroll
                for (int i = 0; i < 2; i++) {
                    wmma::load_matrix_sync(faH[i], &AsH[wm * 32 + i * 16][kk], 40);
                    wmma::load_matrix_sync(faL[i], &AsL[wm * 32 + i * 16][kk], 40);
                }
                #pragma unroll
                for (int j = 0; j < 4; j++) {
                    wmma::fragment<wmma::matrix_b, 16, 16, 16, bf16, wmma::col_major> fbH, fbL;
                    wmma::load_matrix_sync(fbH, &WsH[wn * 64 + j * 16][kk], 40);
                    wmma::load_matrix_sync(fbL, &WsL[wn * 64 + j * 16][kk], 40);
                    #pragma unroll
                    for (int i = 0; i < 2; i++) {
                        wmma::mma_sync(acc[i][j], faH[i], fbH, acc[i][j]);
                        wmma::mma_sync(acc[i][j], faH[i], fbL, acc[i][j]);
                        wmma::mma_sync(acc[i][j], faL[i], fbH, acc[i][j]);
                    }
                }
            }
            __syncthreads();
        }

        float* Cz = ghp + (size_t)slice * (BB * GG);
        #pragma unroll
        for (int i = 0; i < 2; i++)
            #pragma unroll
            for (int j = 0; j < 4; j++)
                wmma::store_matrix_sync(
                    Cz + (size_t)(m0 + wm * 32 + i * 16) * GG + (n0 + wn * 64 + j * 16),
                    acc[i][j], GG, wmma::mem_row_major);

        __threadfence();
        grid_bar();

        // ---- phase 2: gate math; writes fp32 h and split h (and split seq) ----
        for (int idx = blockIdx.x * 256 + tid; idx < BB * HH; idx += NBLK * 256) {
            int b = idx >> 10, j = idx & 1023;
            const float* gib = gi + ((size_t)b * TS + t) * GG;
            float ir = gib[j], iz = gib[HH + j], inn = gib[2 * HH + j];
            float hr = 0.f, hz = 0.f, hn = 0.f;
            #pragma unroll
            for (int s = 0; s < 3; s++) {
                const float* g = ghp + (size_t)s * (BB * GG) + (size_t)b * GG;
                hr += __ldcg(&g[j]);
                hz += __ldcg(&g[HH + j]);
                hn += __ldcg(&g[2 * HH + j]);
            }
            float r = 1.f / (1.f + expf(-(ir + hr)));
            float z = 1.f / (1.f + expf(-(iz + hz)));
            float n = tanhf(inn + r * hn);
            float hp = __ldcg(&h[idx]);
            float hnew = (1.f - z) * n + z * hp;
            h[idx] = hnew;
            bf16 hb = __float2bfloat16(hnew);
            bf16 lb = __float2bfloat16(hnew - __bfloat162float(hb));
            size_t ho = (size_t)b * KP1024 + j;
            hhi[ho] = hb;
            hlo[ho] = lb;
            if (seqhi) {
                size_t so = ((size_t)b * TS + t) * KP1024 + j;
                seqhi[so] = hb;
                seqlo[so] = lb;
            }
        }
        __threadfence();
        grid_bar();
    }
}

// ---------------- attention ---------------------------------------------------
__global__ __launch_bounds__(256) void attention_kernel(const float* __restrict__ qkv,
                                                        float* __restrict__ o) {
    extern __shared__ float sm[];
    float* kv = sm;
    float* sc = sm + NF * DHD;
    int b = blockIdx.x >> 2;
    int h = blockIdx.x & 3;
    int tid = threadIdx.x;
    int lane = tid & 31, w = tid >> 5;
    const float* base = qkv + (size_t)b * NF * GG + h * DHD;

    for (int idx = tid; idx < NF * DHD; idx += 256) {
        int t = idx >> 8, d = idx & 255;
        kv[idx] = base[(size_t)t * GG + HH + d];
    }
    __syncthreads();
    for (int i = w; i < NF; i += 8) {
        float q[8];
        const float* qp = base + (size_t)i * GG;
        #pragma unroll
        for (int c = 0; c < 8; c++) q[c] = qp[lane + 32 * c];
        for (int j = 0; j < NF; j++) {
            const float* kp = kv + j * DHD;
            float s = 0.f;
            #pragma unroll
            for (int c = 0; c < 8; c++) s += q[c] * kp[lane + 32 * c];
            #pragma unroll
            for (int off = 16; off; off >>= 1) s += __shfl_xor_sync(0xffffffffu, s, off);
            if (lane == 0) sc[i * 64 + j] = s * 0.0625f;
        }
    }
    __syncthreads();
    for (int i = w; i < NF; i += 8) {
        float v0 = (lane < NF) ? sc[i * 64 + lane] : -1e30f;
        float v1 = (lane + 32 < NF) ? sc[i * 64 + lane + 32] : -1e30f;
        float m = fmaxf(v0, v1);
        #pragma unroll
        for (int off = 16; off; off >>= 1) m = fmaxf(m, __shfl_xor_sync(0xffffffffu, m, off));
        float e0 = (lane < NF) ? expf(v0 - m) : 0.f;
        float e1 = (lane + 32 < NF) ? expf(v1 - m) : 0.f;
        float ss = e0 + e1;
        #pragma unroll
        for (int off = 16; off; off >>= 1) ss += __shfl_xor_sync(0xffffffffu, ss, off);
        float inv = 1.f / ss;
        if (lane < NF) sc[i * 64 + lane] = e0 * inv;
        if (lane + 32 < NF) sc[i * 64 + lane + 32] = e1 * inv;
    }
    __syncthreads();
    for (int idx = tid; idx < NF * DHD; idx += 256) {
        int t = idx >> 8, d = idx & 255;
        kv[idx] = base[(size_t)t * GG + 2 * HH + d];
    }
    __syncthreads();
    float acc[NF];
    #pragma unroll
    for (int i = 0; i < NF; i++) acc[i] = 0.f;
    int d = tid;
    for (int j = 0; j < NF; j++) {
        float vv = kv[j * DHD + d];
        #pragma unroll
        for (int i = 0; i < NF; i++) acc[i] += sc[i * 64 + j] * vv;
    }
    float* ob = o + (size_t)b * NF * HH + h * DHD + d;
    #pragma unroll
    for (int i = 0; i < NF; i++) ob[(size_t)i * HH] = acc[i];
}

__global__ void mean61_kernel(const float* __restrict__ o, float* __restrict__ obar) {
    int idx = blockIdx.x * 256 + threadIdx.x;
    if (idx >= BB * HH) return;
    int b = idx >> 10, c = idx & 1023;
    const float* p = o + (size_t)b * NF * HH + c;
    float s = 0.f;
    for (int t = 0; t < NF; t++) s += p[(size_t)t * HH];
    obar[idx] = s * (1.f / (float)NF);
}

// ---------------- GRU gate math (decode) ---------------------------------------
__global__ void gru_gate2(const float* __restrict__ gxp, int gx_sk,
                          const float* __restrict__ ghp, int gh_sk,
                          float* __restrict__ h,
                          bf16* __restrict__ hhi, bf16* __restrict__ hlo) {
    int idx = blockIdx.x * 256 + threadIdx.x;
    if (idx >= BB * HH) return;
    int b = idx >> 10, j = idx & 1023;
    float ir = 0.f, iz = 0.f, in = 0.f;
    for (int s = 0; s < gx_sk; s++) {
        const float* g = gxp + (size_t)s * (BB * GG) + (size_t)b * GG;
        ir += g[j]; iz += g[HH + j]; in += g[2 * HH + j];
    }
    float hr = 0.f, hz = 0.f, hn = 0.f;
    for (int s = 0; s < gh_sk; s++) {
        const float* g = ghp + (size_t)s * (BB * GG) + (size_t)b * GG;
        hr += g[j]; hz += g[HH + j]; hn += g[2 * HH + j];
    }
    float r = 1.f / (1.f + expf(-(ir + hr)));
    float z = 1.f / (1.f + expf(-(iz + hz)));
    float n = tanhf(in + r * hn);
    float hp = h[idx];
    float hnew = (1.f - z) * n + z * hp;
    h[idx] = hnew;
    bf16 hb = __float2bfloat16(hnew);
    size_t ho = (size_t)b * KP1024 + j;
    hhi[ho] = hb;
    hlo[ho] = __float2bfloat16(hnew - __bfloat162float(hb));
}

// ---------------- split-K reductions --------------------------------------------
__global__ void reduce_act_kernel(const float* __restrict__ part, int sk, int mn,
                                  float* __restrict__ out) {
    int idx = blockIdx.x * 256 + threadIdx.x;
    if (idx >= mn) return;
    float s = 0.f;
    for (int i = 0; i < sk; i++) s += part[(size_t)i * mn + idx];
    out[idx] = fmaxf(s, 0.f);
}

// relu(sum partials) + addend -> split bf16 (hid)
__global__ void reduce_split_kernel(const float* __restrict__ part, int sk,
                                    const float* __restrict__ addend,
                                    bf16* __restrict__ hi, bf16* __restrict__ lo) {
    int idx = blockIdx.x * 256 + threadIdx.x;
    if (idx >= BB * HH) return;
    int b = idx >> 10, j = idx & 1023;
    float s = 0.f;
    for (int i = 0; i < sk; i++) s += part[(size_t)i * (BB * HH) + idx];
    s = fmaxf(s, 0.f) + addend[idx];
    bf16 hb = __float2bfloat16(s);
    size_t o = (size_t)b * KP1024 + j;
    hi[o] = hb;
    lo[o] = __float2bfloat16(s - __bfloat162float(hb));
}

// ---------------- decode init: split xt + prev6d --------------------------------
__global__ void init_decode(const float* __restrict__ inseq,
                            bf16* __restrict__ xthi, bf16* __restrict__ xtlo,
                            float* __restrict__ p6) {
    int idx = blockIdx.x * 256 + threadIdx.x;
    if (idx >= BB * KP135) return;
    int b = idx / KP135, d = idx % KP135;
    const float* last = inseq + ((size_t)b * TS + (TS - 1)) * DD;
    float v = 0.f;
    if (d < DD) v = last[d];
    else if (d == DD) v = 1.0f;
    bf16 hb = __float2bfloat16(v);
    xthi[idx] = hb;
    xtlo[idx] = __float2bfloat16(v - __bfloat162float(hb));
    if (d < NJ * 6) {
        int j = d / 6, o = d % 6;
        int src = (o < 3) ? (j * 9 + o * 3) : (j * 9 + (o - 3) * 3 + 1);
        p6[(size_t)b * 90 + d] = last[src];
    }
}

// ---------------- spl head layer2 + rot6d (writes split xt) ---------------------
__global__ __launch_bounds__(192) void spl2_rot(const float* __restrict__ z1,
                                                const float* __restrict__ w2,
                                                const float* __restrict__ b2,
                                                float* __restrict__ p6,
                                                bf16* __restrict__ xthi,
                                                bf16* __restrict__ xtlo,
                                                float* __restrict__ out, int step) {
    int bj = blockIdx.x;
    int b = bj / NJ, j = bj % NJ;
    int w = threadIdx.x >> 5, lane = threadIdx.x & 31;
    __shared__ float v6[6];
    const float* zz = z1 + (size_t)b * (NJ * 128) + j * 128;
    const float* ww = w2 + ((size_t)j * 6 + w) * 128;
    float s = 0.f;
    #pragma unroll
    for (int c = 0; c < 4; c++) s += zz[lane + 32 * c] * ww[lane + 32 * c];
    #pragma unroll
    for (int off = 16; off; off >>= 1) s += __shfl_xor_sync(0xffffffffu, s, off);
    if (lane == 0)
        v6[w] = p6[(size_t)b * 90 + j * 6 + w] + s + b2[j * 6 + w];
    __syncthreads();
    if (threadIdx.x < 6) {
        float v = v6[threadIdx.x];
        p6[(size_t)b * 90 + j * 6 + threadIdx.x] = v;
        out[((size_t)b * PREDN + step) * 90 + j * 6 + threadIdx.x] = v;
    }
    if (threadIdx.x == 0) {
        float a1x = v6[0], a2x = v6[1], a1y = v6[2], a2y = v6[3], a1z = v6[4], a2z = v6[5];
        float n1 = fmaxf(sqrtf(a1x*a1x + a1y*a1y + a1z*a1z), 1e-12f);
        float b1x = a1x / n1, b1y = a1y / n1, b1z = a1z / n1;
        float dot = b1x*a2x + b1y*a2y + b1z*a2z;
        float ox = a2x - dot*b1x, oy = a2y - dot*b1y, oz = a2z - dot*b1z;
        float n2 = fmaxf(sqrtf(ox*ox + oy*oy + oz*oz), 1e-12f);
        float b2x = ox / n2, b2y = oy / n2, b2z = oz / n2;
        float b3x = b1y*b2z - b1z*b2y;
        float b3y = b1z*b2x - b1x*b2z;
        float b3z = b1x*b2y - b1y*b2x;
        float rm[9] = { b1x, b2x, b3x, b1y, b2y, b3y, b1z, b2z, b3z };
        size_t base = (size_t)b * KP135 + j * 9;
        #pragma unroll
        for (int c = 0; c < 9; c++) {
            bf16 hb = __float2bfloat16(rm[c]);
            xthi[base + c] = hb;
            xtlo[base + c] = __float2bfloat16(rm[c] - __bfloat162float(hb));
        }
    }
}

// ---------------- host orchestration ---------------------------------------------

static inline void gemm3(const bf16* ahi, const bf16* alo,
                         const bf16* whi, const bf16* wlo,
                         float* C, int M, int N, int KP, int sk) {
    dim3 g(N / 128, M / 128, sk);
    gemm3_kernel<<<g, 256>>>(ahi, alo, whi, wlo, C, M, N, KP);
}

static inline void splitw(const float* W, const float* bias,
                          bf16* hi, bf16* lo, int N, int K, int KP) {
    size_t n = (size_t)N * KP;
    split_w_kernel<<<(int)((n + 255) / 256), 256>>>(W, bias, hi, lo, N, K, KP);
}

static inline void splita(const float* A, bf16* hi, bf16* lo, int M, int K, int KP) {
    size_t n = (size_t)M * KP;
    split_a_kernel<<<(int)((n + 255) / 256), 256>>>(A, hi, lo, M, K, KP);
}

static inline void zerosplit(bf16* hi, bf16* lo, int M, int K, int KP) {
    size_t n = (size_t)M * KP;
    zero_split_kernel<<<(int)((n + 255) / 256), 256>>>(hi, lo, M, K, KP);
}

extern "C" void kernel_launch(void* const* d_in, const int* in_sizes, int n_in,
                              void* d_out, int out_size) {
    const float* poses      = (const float*)d_in[0];
    const float* freq_w     = (const float*)d_in[1];
    const float* freq_b     = (const float*)d_in[2];
    const float* attn_in_w  = (const float*)d_in[3];
    const float* attn_in_b  = (const float*)d_in[4];
    const float* attn_out_w = (const float*)d_in[5];
    const float* attn_out_b = (const float*)d_in[6];
    const float* gru_wih0   = (const float*)d_in[7];
    const float* gru_whh0   = (const float*)d_in[8];
    const float* gru_bih0   = (const float*)d_in[9];
    const float* gru_bhh0   = (const float*)d_in[10];
    const float* gru_wih1   = (const float*)d_in[11];
    const float* gru_whh1   = (const float*)d_in[12];
    const float* gru_bih1   = (const float*)d_in[13];
    const float* gru_bhh1   = (const float*)d_in[14];
    const float* pre_w      = (const float*)d_in[15];
    const float* pre_b      = (const float*)d_in[16];
    const float* spl_w1     = (const float*)d_in[17];
    const float* spl_b1     = (const float*)d_in[18];
    const float* spl_w2     = (const float*)d_in[19];
    const float* spl_b2     = (const float*)d_in[20];
    float* out = (float*)d_out;

    float *pBig, *pSeq, *pIn, *pFrq, *pCos, *pObar, *pMctx, *pH0, *pH1,
          *pGhp, *pGxp, *pPrep, *pSplp, *pZ1, *pP6;
    bf16 *pWhi, *pWlo, *pAhi, *pAlo;
    cudaGetSymbolAddress((void**)&pBig, g_big);
    cudaGetSymbolAddress((void**)&pSeq, g_seq);
    cudaGetSymbolAddress((void**)&pIn,  g_in);
    cudaGetSymbolAddress((void**)&pFrq, g_frq);
    cudaGetSymbolAddress((void**)&pCos, g_cosm);
    cudaGetSymbolAddress((void**)&pObar, g_obar);
    cudaGetSymbolAddress((void**)&pMctx, g_mctx);
    cudaGetSymbolAddress((void**)&pH0, g_h0);
    cudaGetSymbolAddress((void**)&pH1, g_h1);
    cudaGetSymbolAddress((void**)&pGhp, g_ghp);
    cudaGetSymbolAddress((void**)&pGxp, g_gxp);
    cudaGetSymbolAddress((void**)&pPrep, g_prep);
    cudaGetSymbolAddress((void**)&pSplp, g_splp);
    cudaGetSymbolAddress((void**)&pZ1, g_z1);
    cudaGetSymbolAddress((void**)&pP6, g_p6);
    cudaGetSymbolAddress((void**)&pWhi, g_whi);
    cudaGetSymbolAddress((void**)&pWlo, g_wlo);
    cudaGetSymbolAddress((void**)&pAhi, g_ahi);
    cudaGetSymbolAddress((void**)&pAlo, g_alo);

    float* qkv   = pBig;
    float* attno = pBig + (size_t)BB * NF * GG;
    float* gi    = pBig;
    float* feat  = pSeq;

    const int BF = BB * NF;   // 15616
    const int BT = BB * TS;   // 30720

    // ---- one-time weight splits ----
    splitw(attn_in_w, attn_in_b, pWhi + OFF_ATTNIN,  pWlo + OFF_ATTNIN,  GG, HH, KP1024);
    splitw(gru_wih0,  gru_bih0,  pWhi + OFF_WIH0,    pWlo + OFF_WIH0,    GG, DD, KP135);
    splitw(gru_whh0,  gru_bhh0,  pWhi + OFF_WHH0,    pWlo + OFF_WHH0,    GG, HH, KP1024);
    splitw(gru_wih1,  gru_bih1,  pWhi + OFF_WIH1,    pWlo + OFF_WIH1,    GG, HH, KP1024);
    splitw(gru_whh1,  gru_bhh1,  pWhi + OFF_WHH1,    pWlo + OFF_WHH1,    GG, HH, KP1024);
    splitw(freq_w,    freq_b,    pWhi + OFF_FREQ,    pWlo + OFF_FREQ,    HH, DD, KP135);
    splitw(attn_out_w,attn_out_b,pWhi + OFF_ATTNOUT, pWlo + OFF_ATTNOUT, HH, HH, KP1024);
    splitw(pre_w,     pre_b,     pWhi + OFF_PRE,     pWlo + OFF_PRE,     HH, HH, KP1024);
    splitw(spl_w1,    spl_b1,    pWhi + OFF_SPL1,    pWlo + OFF_SPL1,    NJ*128, HH, KP1024);

    // ---- activation split buffer init (ones/zero pad cols) ----
    zerosplit(pAhi + OFFA_SEQ, pAlo + OFFA_SEQ, BT, HH, KP1024);
    zerosplit(pAhi + OFFA_H0,  pAlo + OFFA_H0,  BB, HH, KP1024);
    zerosplit(pAhi + OFFA_H1,  pAlo + OFFA_H1,  BB, HH, KP1024);
    zerosplit(pAhi + OFFA_HID, pAlo + OFFA_HID, BB, HH, KP1024);

    // ---- frequency attention branch ----
    copy_inseq_kernel<<<(BB*TS*DD + 255) / 256, 256>>>(poses, pIn);
    build_cos_kernel<<<(NF*TS + 255) / 256, 256>>>(pCos);
    freq_kernel<<<dim3(BB, NF), 160>>>(pIn, pCos, pFrq);
    splita(pFrq, pAhi + OFFA_FRQ, pAlo + OFFA_FRQ, BF, DD, KP135);
    gemm3(pAhi + OFFA_FRQ, pAlo + OFFA_FRQ, pWhi + OFF_FREQ, pWlo + OFF_FREQ,
          feat, BF, HH, KP135, 1);
    splita(feat, pAhi + OFFA_FEAT, pAlo + OFFA_FEAT, BF, HH, KP1024);
    gemm3(pAhi + OFFA_FEAT, pAlo + OFFA_FEAT, pWhi + OFF_ATTNIN, pWlo + OFF_ATTNIN,
          qkv, BF, GG, KP1024, 1);

    int smem_attn = (NF * DHD + NF * 64) * (int)sizeof(float);
    cudaFuncSetAttribute(attention_kernel, cudaFuncAttributeMaxDynamicSharedMemorySize, smem_attn);
    attention_kernel<<<BB * NHEAD, 256, smem_attn>>>(qkv, attno);
    mean61_kernel<<<(BB*HH + 255) / 256, 256>>>(attno, pObar);
    splita(pObar, pAhi + OFFA_OBAR, pAlo + OFFA_OBAR, BB, HH, KP1024);
    gemm3(pAhi + OFFA_OBAR, pAlo + OFFA_OBAR, pWhi + OFF_ATTNOUT, pWlo + OFF_ATTNOUT,
          pMctx, BB, HH, KP1024, 1);

    // ---- GRU layer 0 (persistent recurrence) ----
    splita(pIn, pAhi + OFFA_IN, pAlo + OFFA_IN, BT, DD, KP135);
    gemm3(pAhi + OFFA_IN, pAlo + OFFA_IN, pWhi + OFF_WIH0, pWlo + OFF_WIH0,
          gi, BT, GG, KP135, 1);
    cudaMemsetAsync(pH0, 0, (size_t)BB * HH * sizeof(float));
    gru_persist_kernel<<<NBLK, 256>>>(gi, pWhi + OFF_WHH0, pWlo + OFF_WHH0,
                                      pH0, pAhi + OFFA_H0, pAlo + OFFA_H0, pGhp,
                                      pAhi + OFFA_SEQ, pAlo + OFFA_SEQ, TS);

    // ---- GRU layer 1 (persistent recurrence) ----
    gemm3(pAhi + OFFA_SEQ, pAlo + OFFA_SEQ, pWhi + OFF_WIH1, pWlo + OFF_WIH1,
          gi, BT, GG, KP1024, 1);
    cudaMemsetAsync(pH1, 0, (size_t)BB * HH * sizeof(float));
    gru_persist_kernel<<<NBLK, 256>>>(gi, pWhi + OFF_WHH1, pWlo + OFF_WHH1,
                                      pH1, pAhi + OFFA_H1, pAlo + OFFA_H1, pGhp,
                                      nullptr, nullptr, TS);

    // ---- autoregressive decode ----
    init_decode<<<(BB*KP135 + 255) / 256, 256>>>(pIn, pAhi + OFFA_XT, pAlo + OFFA_XT, pP6);
    for (int s = 0; s < PREDN; s++) {
        gemm3(pAhi + OFFA_XT, pAlo + OFFA_XT, pWhi + OFF_WIH0, pWlo + OFF_WIH0,
              pGxp, BB, GG, KP135, 2);
        gemm3(pAhi + OFFA_H0, pAlo + OFFA_H0, pWhi + OFF_WHH0, pWlo + OFF_WHH0,
              pGhp, BB, GG, KP1024, 4);
        gru_gate2<<<(BB*HH)/256, 256>>>(pGxp, 2, pGhp, 4, pH0,
                                        pAhi + OFFA_H0, pAlo + OFFA_H0);

        gemm3(pAhi + OFFA_H0, pAlo + OFFA_H0, pWhi + OFF_WIH1, pWlo + OFF_WIH1,
              pGxp, BB, GG, KP1024, 4);
        gemm3(pAhi + OFFA_H1, pAlo + OFFA_H1, pWhi + OFF_WHH1, pWlo + OFF_WHH1,
              pGhp, BB, GG, KP1024, 4);
        gru_gate2<<<(BB*HH)/256, 256>>>(pGxp, 4, pGhp, 4, pH1,
                                        pAhi + OFFA_H1, pAlo + OFFA_H1);

        gemm3(pAhi + OFFA_H1, pAlo + OFFA_H1, pWhi + OFF_PRE, pWlo + OFF_PRE,
              pPrep, BB, HH, KP1024, 8);
        reduce_split_kernel<<<(BB*HH + 255)/256, 256>>>(pPrep, 8, pMctx,
                                                        pAhi + OFFA_HID, pAlo + OFFA_HID);

        gemm3(pAhi + OFFA_HID, pAlo + OFFA_HID, pWhi + OFF_SPL1, pWlo + OFF_SPL1,
              pSplp, BB, NJ*128, KP1024, 8);
        reduce_act_kernel<<<(BB*NJ*128 + 255)/256, 256>>>(pSplp, 8, BB*NJ*128, pZ1);

        spl2_rot<<<BB * NJ, 192>>>(pZ1, spl_w2, spl_b2, pP6,
                                   pAhi + OFFA_XT, pAlo + OFFA_XT, out, s);
    }
}

// round 7
// speedup vs baseline: 3.2814x; 1.1420x over previous
#include <cuda_runtime.h>
#include <cuda_bf16.h>
#include <mma.h>
#include <math.h>

using namespace nvcuda;

#define BB    256
#define TS    120
#define PREDN 24
#define NJ    15
#define HH    1024
#define DD    135
#define NF    61        // rfft length = TS/2+1
#define GG    3072      // 3*H
#define NHEAD 4
#define DHD   256       // H / NHEAD

// padded K (bias column appended, rounded to 32)
#define KP1024 1056
#define KP135  160

#define NBLK  144       // persistent grid size (<= 148 SMs -> co-resident)

// smem stage layout (bf16 elements): AH | AL | WH | WL, each 128x40
#define SOFF_AL 5120
#define SOFF_WH 10240
#define SOFF_WL 15360
#define SST     20480                   // bf16 per stage
#define SMEM_BYTES (2 * SST * 2)        // 81920 B (2 stages)

typedef __nv_bfloat16 bf16;

// ---------------- weight split pools (bf16 hi/lo) ----------------------------
#define OFF_ATTNIN  0ull
#define OFF_WIH0    3244032ull
#define OFF_WHH0    3735552ull
#define OFF_WIH1    6979584ull
#define OFF_WHH1    10223616ull
#define OFF_FREQ    13467648ull
#define OFF_ATTNOUT 13631488ull
#define OFF_PRE     14712832ull
#define OFF_SPL1    15794176ull
#define WPOOL_TOTAL 17821696ull

__device__ bf16 g_whi[WPOOL_TOTAL];
__device__ bf16 g_wlo[WPOOL_TOTAL];

// ---------------- activation split pool (bf16 hi/lo) -------------------------
#define OFFA_IN    0ull          // (BT, 160)
#define OFFA_FRQ   4915200ull    // (BF, 160)
#define OFFA_FEAT  7413760ull    // (BF, 1056)
#define OFFA_SEQ   23904256ull   // (BT, 1056)
#define OFFA_OBAR  56344576ull   // (256, 1056)
#define OFFA_H0    56614912ull   // (256, 1056)
#define OFFA_H1    56885248ull   // (256, 1056)
#define OFFA_HID   57155584ull   // (256, 1056)
#define OFFA_XT    57425920ull   // (256, 160)
#define APOOL_TOTAL 57466880ull

__device__ bf16 g_ahi[APOOL_TOTAL];
__device__ bf16 g_alo[APOOL_TOTAL];

// ---------------- scratch buffers ---------------------------------------------
__device__ float g_big[(size_t)BB * TS * GG];         // gi / qkv / attn-out (aliased)
__device__ float g_seq[(size_t)BB * TS * HH];         // feat fp32 (aliased region)
__device__ float g_in [(size_t)BB * TS * DD];
__device__ float g_frq[(size_t)BB * NF * DD];
__device__ float g_cosm[NF * TS];
__device__ float g_obar[BB * HH];
__device__ float g_mctx[BB * HH];
__device__ float g_h0[BB * HH];
__device__ float g_h1[BB * HH];
__device__ float g_ghp[(size_t)4 * BB * GG];          // partials (gh)
__device__ float g_gxp[(size_t)4 * BB * GG];          // partials (gx)
__device__ float g_prep[(size_t)8 * BB * HH];         // partials (pre)
__device__ float g_splp[(size_t)8 * BB * NJ * 128];   // partials (spl1)
__device__ float g_z1[BB * NJ * 128];
__device__ float g_p6[BB * NJ * 6];

// ---------------- software grid barrier ---------------------------------------
__device__ unsigned g_barcnt = 0;
__device__ unsigned g_barsense = 0;

__device__ __forceinline__ void grid_bar() {
    __syncthreads();
    if (threadIdx.x == 0) {
        unsigned my = *(volatile unsigned*)&g_barsense;
        __threadfence();
        unsigned arrived = atomicAdd(&g_barcnt, 1u);
        if (arrived == NBLK - 1) {
            atomicExch(&g_barcnt, 0u);
            __threadfence();
            atomicExch(&g_barsense, my ^ 1u);
        } else {
            while (*(volatile unsigned*)&g_barsense == my) { }
            __threadfence();
        }
    }
    __syncthreads();
}

// ---------------- cp.async helpers ----------------------------------------------
__device__ __forceinline__ void cp16(bf16* dst, const bf16* src) {
    unsigned saddr = (unsigned)__cvta_generic_to_shared(dst);
    asm volatile("cp.async.cg.shared.global [%0], [%1], 16;\n" :: "r"(saddr), "l"(src));
}
#define CP_COMMIT() asm volatile("cp.async.commit_group;\n" ::: "memory")
#define CP_WAIT1()  asm volatile("cp.async.wait_group 1;\n" ::: "memory")
#define CP_WAIT0()  asm volatile("cp.async.wait_group 0;\n" ::: "memory")

// issue one chunk's loads (A 128x32 hi/lo + W 128x32 hi/lo) into a stage
__device__ __forceinline__ void stage_load(
    bf16* sb, const bf16* __restrict__ Ahi, const bf16* __restrict__ Alo,
    const bf16* __restrict__ Whi, const bf16* __restrict__ Wlo,
    int m0, int n0, int k0, int KP, int tid)
{
    #pragma unroll
    for (int it = 0; it < 2; it++) {
        int slot = tid + it * 256;       // 0..511
        int rw = slot >> 2;              // 0..127
        int col = (slot & 3) << 3;       // 0,8,16,24
        size_t aoff = (size_t)(m0 + rw) * KP + k0 + col;
        size_t woff = (size_t)(n0 + rw) * KP + k0 + col;
        int so = rw * 40 + col;
        cp16(sb + so,           Ahi + aoff);
        cp16(sb + SOFF_AL + so, Alo + aoff);
        cp16(sb + SOFF_WH + so, Whi + woff);
        cp16(sb + SOFF_WL + so, Wlo + woff);
    }
}

// 3-term compensated mma on one stage
__device__ __forceinline__ void mma_stage(
    const bf16* sb, int wm, int wn,
    wmma::fragment<wmma::accumulator, 16, 16, 16, float> (&acc)[2][4])
{
    #pragma unroll
    for (int kk = 0; kk < 32; kk += 16) {
        wmma::fragment<wmma::matrix_a, 16, 16, 16, bf16, wmma::row_major> faH[2], faL[2];
        #pragma unroll
        for (int i = 0; i < 2; i++) {
            wmma::load_matrix_sync(faH[i], sb + (wm * 32 + i * 16) * 40 + kk, 40);
            wmma::load_matrix_sync(faL[i], sb + SOFF_AL + (wm * 32 + i * 16) * 40 + kk, 40);
        }
        #pragma unroll
        for (int j = 0; j < 4; j++) {
            wmma::fragment<wmma::matrix_b, 16, 16, 16, bf16, wmma::col_major> fbH, fbL;
            wmma::load_matrix_sync(fbH, sb + SOFF_WH + (wn * 64 + j * 16) * 40 + kk, 40);
            wmma::load_matrix_sync(fbL, sb + SOFF_WL + (wn * 64 + j * 16) * 40 + kk, 40);
            #pragma unroll
            for (int i = 0; i < 2; i++) {
                wmma::mma_sync(acc[i][j], faH[i], fbH, acc[i][j]);
                wmma::mma_sync(acc[i][j], faH[i], fbL, acc[i][j]);
                wmma::mma_sync(acc[i][j], faL[i], fbH, acc[i][j]);
            }
        }
    }
}

// ---------------- small utility kernels -------------------------------------

__global__ void copy_inseq_kernel(const float* __restrict__ poses, float* __restrict__ dst) {
    int idx = blockIdx.x * 256 + threadIdx.x;
    if (idx >= BB * TS * DD) return;
    int d = idx % DD;
    int t = (idx / DD) % TS;
    int b = idx / (TS * DD);
    dst[idx] = poses[((size_t)b * (TS + PREDN) + t) * DD + d];
}

__global__ void build_cos_kernel(float* __restrict__ cosm) {
    int idx = blockIdx.x * 256 + threadIdx.x;
    if (idx >= NF * TS) return;
    int f = idx / TS, t = idx % TS;
    cosm[idx] = (float)cos(2.0 * 3.14159265358979323846 * (double)(f * t) / (double)TS);
}

__global__ void freq_kernel(const float* __restrict__ inseq, const float* __restrict__ cosm,
                            float* __restrict__ freq) {
    int b = blockIdx.x, f = blockIdx.y, d = threadIdx.x;
    if (d >= DD) return;
    const float* xp = inseq + (size_t)b * TS * DD + d;
    const float* cp = cosm + f * TS;
    float s = 0.f;
    #pragma unroll 4
    for (int t = 0; t < TS; t++) s += cp[t] * xp[(size_t)t * DD];
    freq[((size_t)b * NF + f) * DD + d] = s;
}

// ---------------- weight/activation splitters ---------------------------------
__global__ void split_w_kernel(const float* __restrict__ W, const float* __restrict__ bias,
                               bf16* __restrict__ hi, bf16* __restrict__ lo,
                               int N, int K, int KP) {
    size_t idx = (size_t)blockIdx.x * 256 + threadIdx.x;
    if (idx >= (size_t)N * KP) return;
    int k = (int)(idx % KP);
    int n = (int)(idx / KP);
    float v = 0.f;
    if (k < K) v = W[(size_t)n * K + k];
    else if (k == K) v = bias[n];
    bf16 h = __float2bfloat16(v);
    hi[idx] = h;
    lo[idx] = __float2bfloat16(v - __bfloat162float(h));
}

__global__ void split_a_kernel(const float* __restrict__ A,
                               bf16* __restrict__ hi, bf16* __restrict__ lo,
                               int M, int K, int KP) {
    size_t idx = (size_t)blockIdx.x * 256 + threadIdx.x;
    if (idx >= (size_t)M * KP) return;
    int k = (int)(idx % KP);
    int m = (int)(idx / KP);
    float v = 0.f;
    if (k < K) v = A[(size_t)m * K + k];
    else if (k == K) v = 1.0f;
    bf16 h = __float2bfloat16(v);
    hi[idx] = h;
    lo[idx] = __float2bfloat16(v - __bfloat162float(h));
}

__global__ void zero_split_kernel(bf16* __restrict__ hi, bf16* __restrict__ lo,
                                  int M, int K, int KP) {
    size_t idx = (size_t)blockIdx.x * 256 + threadIdx.x;
    if (idx >= (size_t)M * KP) return;
    int k = (int)(idx % KP);
    float v = (k == K) ? 1.0f : 0.0f;
    hi[idx] = __float2bfloat16(v);
    lo[idx] = __float2bfloat16(0.0f);
}

// ---------------- double-buffered pre-split bf16 GEMM --------------------------
// C = A(M,KP) * W(N,KP)^T, split-K via gridDim.z (slice z writes C + z*M*N).
__global__ __launch_bounds__(256, 2) void gemm4_kernel(
    const bf16* __restrict__ Ahi, const bf16* __restrict__ Alo,
    const bf16* __restrict__ Whi, const bf16* __restrict__ Wlo,
    float* __restrict__ C, int M, int N, int KP)
{
    extern __shared__ __align__(16) bf16 sm4[];
    int tid = threadIdx.x;
    int warp = tid >> 5;
    int wm = warp >> 1, wn = warp & 1;
    int m0 = blockIdx.y * 128, n0 = blockIdx.x * 128;

    wmma::fragment<wmma::accumulator, 16, 16, 16, float> acc[2][4];
    #pragma unroll
    for (int i = 0; i < 2; i++)
        #pragma unroll
        for (int j = 0; j < 4; j++)
            wmma::fill_fragment(acc[i][j], 0.0f);

    int CH  = KP >> 5;
    int cpz = (CH + gridDim.z - 1) / gridDim.z;
    int c0  = blockIdx.z * cpz;
    int c1  = c0 + cpz; if (c1 > CH) c1 = CH;
    int nch = c1 - c0;

    if (nch > 0) {
        stage_load(sm4, Ahi, Alo, Whi, Wlo, m0, n0, c0 << 5, KP, tid);
        CP_COMMIT();
    }
    for (int i = 0; i < nch; i++) {
        bf16* sb = sm4 + (i & 1) * SST;
        if (i + 1 < nch) {
            stage_load(sm4 + ((i + 1) & 1) * SST, Ahi, Alo, Whi, Wlo,
                       m0, n0, (c0 + i + 1) << 5, KP, tid);
            CP_COMMIT();
            CP_WAIT1();
        } else {
            CP_WAIT0();
        }
        __syncthreads();
        mma_stage(sb, wm, wn, acc);
        __syncthreads();
    }

    float* Cz = C + (size_t)blockIdx.z * M * N;
    #pragma unroll
    for (int i = 0; i < 2; i++)
        #pragma unroll
        for (int j = 0; j < 4; j++)
            wmma::store_matrix_sync(
                Cz + (size_t)(m0 + wm * 32 + i * 16) * N + (n0 + wn * 64 + j * 16),
                acc[i][j], N, wmma::mem_row_major);
}

// ---------------- persistent GRU recurrence (one launch per layer) -----------
__global__ __launch_bounds__(256, 1) void gru_persist_kernel(
    const float* __restrict__ gi,          // (B, TS, GG), bih fused
    const bf16* __restrict__ Whi,          // (GG, KP1024), bhh in col HH
    const bf16* __restrict__ Wlo,
    float* __restrict__ h,                 // (B, HH) fp32, pre-zeroed
    bf16* __restrict__ hhi,                // (B, KP1024), pre-inited
    bf16* __restrict__ hlo,
    float* __restrict__ ghp,               // (3, B, GG) partials
    bf16* __restrict__ seqhi,              // (B, TS, KP1024) or null
    bf16* __restrict__ seqlo,
    int nsteps)
{
    extern __shared__ __align__(16) bf16 sm4[];
    int tid = threadIdx.x;
    int warp = tid >> 5;
    int wm = warp >> 1, wn = warp & 1;
    int tile  = blockIdx.x % 48;
    int slice = blockIdx.x / 48;           // 0..2
    int m0 = (tile / 24) * 128;
    int n0 = (tile % 24) * 128;
    const int c0 = slice * 11;

    for (int t = 0; t < nsteps; t++) {
        // ---- phase 1: partial gh = h @ Whh^T over this k-slice ----
        wmma::fragment<wmma::accumulator, 16, 16, 16, float> acc[2][4];
        #pragma unroll
        for (int i = 0; i < 2; i++)
            #pragma unroll
            for (int j = 0; j < 4; j++)
                wmma::fill_fragment(acc[i][j], 0.0f);

        stage_load(sm4, hhi, hlo, Whi, Wlo, m0, n0, c0 << 5, KP1024, tid);
        CP_COMMIT();
        #pragma unroll
        for (int i = 0; i < 11; i++) {
            bf16* sb = sm4 + (i & 1) * SST;
            if (i + 1 < 11) {
                stage_load(sm4 + ((i + 1) & 1) * SST, hhi, hlo, Whi, Wlo,
                           m0, n0, (c0 + i + 1) << 5, KP1024, tid);
                CP_COMMIT();
                CP_WAIT1();
            } else {
                CP_WAIT0();
            }
            __syncthreads();
            mma_stage(sb, wm, wn, acc);
            __syncthreads();
        }

        float* Cz = ghp + (size_t)slice * (BB * GG);
        #pragma unroll
        for (int i = 0; i < 2; i++)
            #pragma unroll
            for (int j = 0; j < 4; j++)
                wmma::store_matrix_sync(
                    Cz + (size_t)(m0 + wm * 32 + i * 16) * GG + (n0 + wn * 64 + j * 16),
                    acc[i][j], GG, wmma::mem_row_major);

        __threadfence();
        grid_bar();

        // ---- phase 2: gate math; writes fp32 h and split h (and split seq) ----
        for (int idx = blockIdx.x * 256 + tid; idx < BB * HH; idx += NBLK * 256) {
            int b = idx >> 10, j = idx & 1023;
            const float* gib = gi + ((size_t)b * TS + t) * GG;
            float ir = gib[j], iz = gib[HH + j], inn = gib[2 * HH + j];
            float hr = 0.f, hz = 0.f, hn = 0.f;
            #pragma unroll
            for (int s = 0; s < 3; s++) {
                const float* g = ghp + (size_t)s * (BB * GG) + (size_t)b * GG;
                hr += __ldcg(&g[j]);
                hz += __ldcg(&g[HH + j]);
                hn += __ldcg(&g[2 * HH + j]);
            }
            float r = 1.f / (1.f + expf(-(ir + hr)));
            float z = 1.f / (1.f + expf(-(iz + hz)));
            float n = tanhf(inn + r * hn);
            float hp = __ldcg(&h[idx]);
            float hnew = (1.f - z) * n + z * hp;
            h[idx] = hnew;
            bf16 hb = __float2bfloat16(hnew);
            bf16 lb = __float2bfloat16(hnew - __bfloat162float(hb));
            size_t ho = (size_t)b * KP1024 + j;
            hhi[ho] = hb;
            hlo[ho] = lb;
            if (seqhi) {
                size_t so = ((size_t)b * TS + t) * KP1024 + j;
                seqhi[so] = hb;
                seqlo[so] = lb;
            }
        }
        __threadfence();
        grid_bar();
    }
}

// ---------------- attention ---------------------------------------------------
__global__ __launch_bounds__(256) void attention_kernel(const float* __restrict__ qkv,
                                                        float* __restrict__ o) {
    extern __shared__ float sm[];
    float* kv = sm;
    float* sc = sm + NF * DHD;
    int b = blockIdx.x >> 2;
    int h = blockIdx.x & 3;
    int tid = threadIdx.x;
    int lane = tid & 31, w = tid >> 5;
    const float* base = qkv + (size_t)b * NF * GG + h * DHD;

    for (int idx = tid; idx < NF * DHD; idx += 256) {
        int t = idx >> 8, d = idx & 255;
        kv[idx] = base[(size_t)t * GG + HH + d];
    }
    __syncthreads();
    for (int i = w; i < NF; i += 8) {
        float q[8];
        const float* qp = base + (size_t)i * GG;
        #pragma unroll
        for (int c = 0; c < 8; c++) q[c] = qp[lane + 32 * c];
        for (int j = 0; j < NF; j++) {
            const float* kp = kv + j * DHD;
            float s = 0.f;
            #pragma unroll
            for (int c = 0; c < 8; c++) s += q[c] * kp[lane + 32 * c];
            #pragma unroll
            for (int off = 16; off; off >>= 1) s += __shfl_xor_sync(0xffffffffu, s, off);
            if (lane == 0) sc[i * 64 + j] = s * 0.0625f;
        }
    }
    __syncthreads();
    for (int i = w; i < NF; i += 8) {
        float v0 = (lane < NF) ? sc[i * 64 + lane] : -1e30f;
        float v1 = (lane + 32 < NF) ? sc[i * 64 + lane + 32] : -1e30f;
        float m = fmaxf(v0, v1);
        #pragma unroll
        for (int off = 16; off; off >>= 1) m = fmaxf(m, __shfl_xor_sync(0xffffffffu, m, off));
        float e0 = (lane < NF) ? expf(v0 - m) : 0.f;
        float e1 = (lane + 32 < NF) ? expf(v1 - m) : 0.f;
        float ss = e0 + e1;
        #pragma unroll
        for (int off = 16; off; off >>= 1) ss += __shfl_xor_sync(0xffffffffu, ss, off);
        float inv = 1.f / ss;
        if (lane < NF) sc[i * 64 + lane] = e0 * inv;
        if (lane + 32 < NF) sc[i * 64 + lane + 32] = e1 * inv;
    }
    __syncthreads();
    for (int idx = tid; idx < NF * DHD; idx += 256) {
        int t = idx >> 8, d = idx & 255;
        kv[idx] = base[(size_t)t * GG + 2 * HH + d];
    }
    __syncthreads();
    float acc[NF];
    #pragma unroll
    for (int i = 0; i < NF; i++) acc[i] = 0.f;
    int d = tid;
    for (int j = 0; j < NF; j++) {
        float vv = kv[j * DHD + d];
        #pragma unroll
        for (int i = 0; i < NF; i++) acc[i] += sc[i * 64 + j] * vv;
    }
    float* ob = o + (size_t)b * NF * HH + h * DHD + d;
    #pragma unroll
    for (int i = 0; i < NF; i++) ob[(size_t)i * HH] = acc[i];
}

__global__ void mean61_kernel(const float* __restrict__ o, float* __restrict__ obar) {
    int idx = blockIdx.x * 256 + threadIdx.x;
    if (idx >= BB * HH) return;
    int b = idx >> 10, c = idx & 1023;
    const float* p = o + (size_t)b * NF * HH + c;
    float s = 0.f;
    for (int t = 0; t < NF; t++) s += p[(size_t)t * HH];
    obar[idx] = s * (1.f / (float)NF);
}

// ---------------- GRU gate math (decode) ---------------------------------------
__global__ void gru_gate2(const float* __restrict__ gxp, int gx_sk,
                          const float* __restrict__ ghp, int gh_sk,
                          float* __restrict__ h,
                          bf16* __restrict__ hhi, bf16* __restrict__ hlo) {
    int idx = blockIdx.x * 256 + threadIdx.x;
    if (idx >= BB * HH) return;
    int b = idx >> 10, j = idx & 1023;
    float ir = 0.f, iz = 0.f, in = 0.f;
    for (int s = 0; s < gx_sk; s++) {
        const float* g = gxp + (size_t)s * (BB * GG) + (size_t)b * GG;
        ir += g[j]; iz += g[HH + j]; in += g[2 * HH + j];
    }
    float hr = 0.f, hz = 0.f, hn = 0.f;
    for (int s = 0; s < gh_sk; s++) {
        const float* g = ghp + (size_t)s * (BB * GG) + (size_t)b * GG;
        hr += g[j]; hz += g[HH + j]; hn += g[2 * HH + j];
    }
    float r = 1.f / (1.f + expf(-(ir + hr)));
    float z = 1.f / (1.f + expf(-(iz + hz)));
    float n = tanhf(in + r * hn);
    float hp = h[idx];
    float hnew = (1.f - z) * n + z * hp;
    h[idx] = hnew;
    bf16 hb = __float2bfloat16(hnew);
    size_t ho = (size_t)b * KP1024 + j;
    hhi[ho] = hb;
    hlo[ho] = __float2bfloat16(hnew - __bfloat162float(hb));
}

// ---------------- split-K reductions --------------------------------------------
__global__ void reduce_act_kernel(const float* __restrict__ part, int sk, int mn,
                                  float* __restrict__ out) {
    int idx = blockIdx.x * 256 + threadIdx.x;
    if (idx >= mn) return;
    float s = 0.f;
    for (int i = 0; i < sk; i++) s += part[(size_t)i * mn + idx];
    out[idx] = fmaxf(s, 0.f);
}

__global__ void reduce_split_kernel(const float* __restrict__ part, int sk,
                                    const float* __restrict__ addend,
                                    bf16* __restrict__ hi, bf16* __restrict__ lo) {
    int idx = blockIdx.x * 256 + threadIdx.x;
    if (idx >= BB * HH) return;
    int b = idx >> 10, j = idx & 1023;
    float s = 0.f;
    for (int i = 0; i < sk; i++) s += part[(size_t)i * (BB * HH) + idx];
    s = fmaxf(s, 0.f) + addend[idx];
    bf16 hb = __float2bfloat16(s);
    size_t o = (size_t)b * KP1024 + j;
    hi[o] = hb;
    lo[o] = __float2bfloat16(s - __bfloat162float(hb));
}

// ---------------- decode init ---------------------------------------------------
__global__ void init_decode(const float* __restrict__ inseq,
                            bf16* __restrict__ xthi, bf16* __restrict__ xtlo,
                            float* __restrict__ p6) {
    int idx = blockIdx.x * 256 + threadIdx.x;
    if (idx >= BB * KP135) return;
    int b = idx / KP135, d = idx % KP135;
    const float* last = inseq + ((size_t)b * TS + (TS - 1)) * DD;
    float v = 0.f;
    if (d < DD) v = last[d];
    else if (d == DD) v = 1.0f;
    bf16 hb = __float2bfloat16(v);
    xthi[idx] = hb;
    xtlo[idx] = __float2bfloat16(v - __bfloat162float(hb));
    if (d < NJ * 6) {
        int j = d / 6, o = d % 6;
        int src = (o < 3) ? (j * 9 + o * 3) : (j * 9 + (o - 3) * 3 + 1);
        p6[(size_t)b * 90 + d] = last[src];
    }
}

// ---------------- spl head layer2 + rot6d (writes split xt) ---------------------
__global__ __launch_bounds__(192) void spl2_rot(const float* __restrict__ z1,
                                                const float* __restrict__ w2,
                                                const float* __restrict__ b2,
                                                float* __restrict__ p6,
                                                bf16* __restrict__ xthi,
                                                bf16* __restrict__ xtlo,
                                                float* __restrict__ out, int step) {
    int bj = blockIdx.x;
    int b = bj / NJ, j = bj % NJ;
    int w = threadIdx.x >> 5, lane = threadIdx.x & 31;
    __shared__ float v6[6];
    const float* zz = z1 + (size_t)b * (NJ * 128) + j * 128;
    const float* ww = w2 + ((size_t)j * 6 + w) * 128;
    float s = 0.f;
    #pragma unroll
    for (int c = 0; c < 4; c++) s += zz[lane + 32 * c] * ww[lane + 32 * c];
    #pragma unroll
    for (int off = 16; off; off >>= 1) s += __shfl_xor_sync(0xffffffffu, s, off);
    if (lane == 0)
        v6[w] = p6[(size_t)b * 90 + j * 6 + w] + s + b2[j * 6 + w];
    __syncthreads();
    if (threadIdx.x < 6) {
        float v = v6[threadIdx.x];
        p6[(size_t)b * 90 + j * 6 + threadIdx.x] = v;
        out[((size_t)b * PREDN + step) * 90 + j * 6 + threadIdx.x] = v;
    }
    if (threadIdx.x == 0) {
        float a1x = v6[0], a2x = v6[1], a1y = v6[2], a2y = v6[3], a1z = v6[4], a2z = v6[5];
        float n1 = fmaxf(sqrtf(a1x*a1x + a1y*a1y + a1z*a1z), 1e-12f);
        float b1x = a1x / n1, b1y = a1y / n1, b1z = a1z / n1;
        float dot = b1x*a2x + b1y*a2y + b1z*a2z;
        float ox = a2x - dot*b1x, oy = a2y - dot*b1y, oz = a2z - dot*b1z;
        float n2 = fmaxf(sqrtf(ox*ox + oy*oy + oz*oz), 1e-12f);
        float b2x = ox / n2, b2y = oy / n2, b2z = oz / n2;
        float b3x = b1y*b2z - b1z*b2y;
        float b3y = b1z*b2x - b1x*b2z;
        float b3z = b1x*b2y - b1y*b2x;
        float rm[9] = { b1x, b2x, b3x, b1y, b2y, b3y, b1z, b2z, b3z };
        size_t base = (size_t)b * KP135 + j * 9;
        #pragma unroll
        for (int c = 0; c < 9; c++) {
            bf16 hb = __float2bfloat16(rm[c]);
            xthi[base + c] = hb;
            xtlo[base + c] = __float2bfloat16(rm[c] - __bfloat162float(hb));
        }
    }
}

// ---------------- host orchestration ---------------------------------------------

static inline void gemm4(const bf16* ahi, const bf16* alo,
                         const bf16* whi, const bf16* wlo,
                         float* C, int M, int N, int KP, int sk) {
    dim3 g(N / 128, M / 128, sk);
    gemm4_kernel<<<g, 256, SMEM_BYTES>>>(ahi, alo, whi, wlo, C, M, N, KP);
}

static inline void splitw(const float* W, const float* bias,
                          bf16* hi, bf16* lo, int N, int K, int KP) {
    size_t n = (size_t)N * KP;
    split_w_kernel<<<(int)((n + 255) / 256), 256>>>(W, bias, hi, lo, N, K, KP);
}

static inline void splita(const float* A, bf16* hi, bf16* lo, int M, int K, int KP) {
    size_t n = (size_t)M * KP;
    split_a_kernel<<<(int)((n + 255) / 256), 256>>>(A, hi, lo, M, K, KP);
}

static inline void zerosplit(bf16* hi, bf16* lo, int M, int K, int KP) {
    size_t n = (size_t)M * KP;
    zero_split_kernel<<<(int)((n + 255) / 256), 256>>>(hi, lo, M, K, KP);
}

extern "C" void kernel_launch(void* const* d_in, const int* in_sizes, int n_in,
                              void* d_out, int out_size) {
    const float* poses      = (const float*)d_in[0];
    const float* freq_w     = (const float*)d_in[1];
    const float* freq_b     = (const float*)d_in[2];
    const float* attn_in_w  = (const float*)d_in[3];
    const float* attn_in_b  = (const float*)d_in[4];
    const float* attn_out_w = (const float*)d_in[5];
    const float* attn_out_b = (const float*)d_in[6];
    const float* gru_wih0   = (const float*)d_in[7];
    const float* gru_whh0   = (const float*)d_in[8];
    const float* gru_bih0   = (const float*)d_in[9];
    const float* gru_bhh0   = (const float*)d_in[10];
    const float* gru_wih1   = (const float*)d_in[11];
    const float* gru_whh1   = (const float*)d_in[12];
    const float* gru_bih1   = (const float*)d_in[13];
    const float* gru_bhh1   = (const float*)d_in[14];
    const float* pre_w      = (const float*)d_in[15];
    const float* pre_b      = (const float*)d_in[16];
    const float* spl_w1     = (const float*)d_in[17];
    const float* spl_b1     = (const float*)d_in[18];
    const float* spl_w2     = (const float*)d_in[19];
    const float* spl_b2     = (const float*)d_in[20];
    float* out = (float*)d_out;

    float *pBig, *pSeq, *pIn, *pFrq, *pCos, *pObar, *pMctx, *pH0, *pH1,
          *pGhp, *pGxp, *pPrep, *pSplp, *pZ1, *pP6;
    bf16 *pWhi, *pWlo, *pAhi, *pAlo;
    cudaGetSymbolAddress((void**)&pBig, g_big);
    cudaGetSymbolAddress((void**)&pSeq, g_seq);
    cudaGetSymbolAddress((void**)&pIn,  g_in);
    cudaGetSymbolAddress((void**)&pFrq, g_frq);
    cudaGetSymbolAddress((void**)&pCos, g_cosm);
    cudaGetSymbolAddress((void**)&pObar, g_obar);
    cudaGetSymbolAddress((void**)&pMctx, g_mctx);
    cudaGetSymbolAddress((void**)&pH0, g_h0);
    cudaGetSymbolAddress((void**)&pH1, g_h1);
    cudaGetSymbolAddress((void**)&pGhp, g_ghp);
    cudaGetSymbolAddress((void**)&pGxp, g_gxp);
    cudaGetSymbolAddress((void**)&pPrep, g_prep);
    cudaGetSymbolAddress((void**)&pSplp, g_splp);
    cudaGetSymbolAddress((void**)&pZ1, g_z1);
    cudaGetSymbolAddress((void**)&pP6, g_p6);
    cudaGetSymbolAddress((void**)&pWhi, g_whi);
    cudaGetSymbolAddress((void**)&pWlo, g_wlo);
    cudaGetSymbolAddress((void**)&pAhi, g_ahi);
    cudaGetSymbolAddress((void**)&pAlo, g_alo);

    // opt-in dynamic smem (>48KB)
    cudaFuncSetAttribute(gemm4_kernel, cudaFuncAttributeMaxDynamicSharedMemorySize, SMEM_BYTES);
    cudaFuncSetAttribute(gru_persist_kernel, cudaFuncAttributeMaxDynamicSharedMemorySize, SMEM_BYTES);

    float* qkv   = pBig;
    float* attno = pBig + (size_t)BB * NF * GG;
    float* gi    = pBig;
    float* feat  = pSeq;

    const int BF = BB * NF;   // 15616
    const int BT = BB * TS;   // 30720

    // ---- one-time weight splits ----
    splitw(attn_in_w, attn_in_b, pWhi + OFF_ATTNIN,  pWlo + OFF_ATTNIN,  GG, HH, KP1024);
    splitw(gru_wih0,  gru_bih0,  pWhi + OFF_WIH0,    pWlo + OFF_WIH0,    GG, DD, KP135);
    splitw(gru_whh0,  gru_bhh0,  pWhi + OFF_WHH0,    pWlo + OFF_WHH0,    GG, HH, KP1024);
    splitw(gru_wih1,  gru_bih1,  pWhi + OFF_WIH1,    pWlo + OFF_WIH1,    GG, HH, KP1024);
    splitw(gru_whh1,  gru_bhh1,  pWhi + OFF_WHH1,    pWlo + OFF_WHH1,    GG, HH, KP1024);
    splitw(freq_w,    freq_b,    pWhi + OFF_FREQ,    pWlo + OFF_FREQ,    HH, DD, KP135);
    splitw(attn_out_w,attn_out_b,pWhi + OFF_ATTNOUT, pWlo + OFF_ATTNOUT, HH, HH, KP1024);
    splitw(pre_w,     pre_b,     pWhi + OFF_PRE,     pWlo + OFF_PRE,     HH, HH, KP1024);
    splitw(spl_w1,    spl_b1,    pWhi + OFF_SPL1,    pWlo + OFF_SPL1,    NJ*128, HH, KP1024);

    // ---- activation split buffer init (ones/zero pad cols) ----
    zerosplit(pAhi + OFFA_SEQ, pAlo + OFFA_SEQ, BT, HH, KP1024);
    zerosplit(pAhi + OFFA_H0,  pAlo + OFFA_H0,  BB, HH, KP1024);
    zerosplit(pAhi + OFFA_H1,  pAlo + OFFA_H1,  BB, HH, KP1024);
    zerosplit(pAhi + OFFA_HID, pAlo + OFFA_HID, BB, HH, KP1024);

    // ---- frequency attention branch ----
    copy_inseq_kernel<<<(BB*TS*DD + 255) / 256, 256>>>(poses, pIn);
    build_cos_kernel<<<(NF*TS + 255) / 256, 256>>>(pCos);
    freq_kernel<<<dim3(BB, NF), 160>>>(pIn, pCos, pFrq);
    splita(pFrq, pAhi + OFFA_FRQ, pAlo + OFFA_FRQ, BF, DD, KP135);
    gemm4(pAhi + OFFA_FRQ, pAlo + OFFA_FRQ, pWhi + OFF_FREQ, pWlo + OFF_FREQ,
          feat, BF, HH, KP135, 1);
    splita(feat, pAhi + OFFA_FEAT, pAlo + OFFA_FEAT, BF, HH, KP1024);
    gemm4(pAhi + OFFA_FEAT, pAlo + OFFA_FEAT, pWhi + OFF_ATTNIN, pWlo + OFF_ATTNIN,
          qkv, BF, GG, KP1024, 1);

    int smem_attn = (NF * DHD + NF * 64) * (int)sizeof(float);
    cudaFuncSetAttribute(attention_kernel, cudaFuncAttributeMaxDynamicSharedMemorySize, smem_attn);
    attention_kernel<<<BB * NHEAD, 256, smem_attn>>>(qkv, attno);
    mean61_kernel<<<(BB*HH + 255) / 256, 256>>>(attno, pObar);
    splita(pObar, pAhi + OFFA_OBAR, pAlo + OFFA_OBAR, BB, HH, KP1024);
    gemm4(pAhi + OFFA_OBAR, pAlo + OFFA_OBAR, pWhi + OFF_ATTNOUT, pWlo + OFF_ATTNOUT,
          pMctx, BB, HH, KP1024, 1);

    // ---- GRU layer 0 (persistent recurrence) ----
    splita(pIn, pAhi + OFFA_IN, pAlo + OFFA_IN, BT, DD, KP135);
    gemm4(pAhi + OFFA_IN, pAlo + OFFA_IN, pWhi + OFF_WIH0, pWlo + OFF_WIH0,
          gi, BT, GG, KP135, 1);
    cudaMemsetAsync(pH0, 0, (size_t)BB * HH * sizeof(float));
    gru_persist_kernel<<<NBLK, 256, SMEM_BYTES>>>(gi, pWhi + OFF_WHH0, pWlo + OFF_WHH0,
                                      pH0, pAhi + OFFA_H0, pAlo + OFFA_H0, pGhp,
                                      pAhi + OFFA_SEQ, pAlo + OFFA_SEQ, TS);

    // ---- GRU layer 1 (persistent recurrence) ----
    gemm4(pAhi + OFFA_SEQ, pAlo + OFFA_SEQ, pWhi + OFF_WIH1, pWlo + OFF_WIH1,
          gi, BT, GG, KP1024, 1);
    cudaMemsetAsync(pH1, 0, (size_t)BB * HH * sizeof(float));
    gru_persist_kernel<<<NBLK, 256, SMEM_BYTES>>>(gi, pWhi + OFF_WHH1, pWlo + OFF_WHH1,
                                      pH1, pAhi + OFFA_H1, pAlo + OFFA_H1, pGhp,
                                      nullptr, nullptr, TS);

    // ---- autoregressive decode ----
    init_decode<<<(BB*KP135 + 255) / 256, 256>>>(pIn, pAhi + OFFA_XT, pAlo + OFFA_XT, pP6);
    for (int s = 0; s < PREDN; s++) {
        gemm4(pAhi + OFFA_XT, pAlo + OFFA_XT, pWhi + OFF_WIH0, pWlo + OFF_WIH0,
              pGxp, BB, GG, KP135, 2);
        gemm4(pAhi + OFFA_H0, pAlo + OFFA_H0, pWhi + OFF_WHH0, pWlo + OFF_WHH0,
              pGhp, BB, GG, KP1024, 4);
        gru_gate2<<<(BB*HH)/256, 256>>>(pGxp, 2, pGhp, 4, pH0,
                                        pAhi + OFFA_H0, pAlo + OFFA_H0);

        gemm4(pAhi + OFFA_H0, pAlo + OFFA_H0, pWhi + OFF_WIH1, pWlo + OFF_WIH1,
              pGxp, BB, GG, KP1024, 4);
        gemm4(pAhi + OFFA_H1, pAlo + OFFA_H1, pWhi + OFF_WHH1, pWlo + OFF_WHH1,
              pGhp, BB, GG, KP1024, 4);
        gru_gate2<<<(BB*HH)/256, 256>>>(pGxp, 4, pGhp, 4, pH1,
                                        pAhi + OFFA_H1, pAlo + OFFA_H1);

        gemm4(pAhi + OFFA_H1, pAlo + OFFA_H1, pWhi + OFF_PRE, pWlo + OFF_PRE,
              pPrep, BB, HH, KP1024, 8);
        reduce_split_kernel<<<(BB*HH + 255)/256, 256>>>(pPrep, 8, pMctx,
                                                        pAhi + OFFA_HID, pAlo + OFFA_HID);

        gemm4(pAhi + OFFA_HID, pAlo + OFFA_HID, pWhi + OFF_SPL1, pWlo + OFF_SPL1,
              pSplp, BB, NJ*128, KP1024, 8);
        reduce_act_kernel<<<(BB*NJ*128 + 255)/256, 256>>>(pSplp, 8, BB*NJ*128, pZ1);

        spl2_rot<<<BB * NJ, 192>>>(pZ1, spl_w2, spl_b2, pP6,
                                   pAhi + OFFA_XT, pAlo + OFFA_XT, out, s);
    }
}